// round 1
// baseline (speedup 1.0000x reference)
#include <cuda_runtime.h>
#include <cuda_bf16.h>
#include <math.h>

// Problem constants
#define D_   1024
#define H_   16
#define V_   50257
#define L_   4
#define B_   2
#define S_   1024
#define DK_  64
#define DFF_ 4096
#define NTOK (B_ * S_)      // 2048
#define NEGF (-3.402823466e38f)

// ---------------------------------------------------------------------------
// Device scratch (no allocations allowed)
// ---------------------------------------------------------------------------
__device__ float g_x [NTOK * D_];        // residual stream
__device__ float g_q [NTOK * D_];
__device__ float g_k [NTOK * D_];
__device__ float g_v [NTOK * D_];
__device__ float g_y [NTOK * D_];
__device__ float g_ln[NTOK * D_];
__device__ float g_h1[NTOK * DFF_];
__device__ float g_p [(size_t)B_ * H_ * S_ * S_];   // attention probs scratch

__device__ __forceinline__ float gelu_exact(float v) {
    return 0.5f * v * (1.0f + erff(v * 0.70710678118654752440f));
}

// ---------------------------------------------------------------------------
// Embedding: x[b,s,:] = te[idx[b,s],:] + pe[s,:]
// ---------------------------------------------------------------------------
__global__ void embed_kernel(const int* __restrict__ idx,
                             const float* __restrict__ te,
                             const float* __restrict__ pe,
                             float* __restrict__ x) {
    int row = blockIdx.x;                 // 0..NTOK-1
    int s   = row % S_;
    int tok = idx[row];
    int c   = threadIdx.x * 4;            // 256 threads * 4 = 1024
    float4 t = *(const float4*)(te + (size_t)tok * D_ + c);
    float4 p = *(const float4*)(pe + (size_t)s   * D_ + c);
    float4 o = make_float4(t.x + p.x, t.y + p.y, t.z + p.z, t.w + p.w);
    *(float4*)(x + (size_t)row * D_ + c) = o;
}

// ---------------------------------------------------------------------------
// Generic SGEMM: C[M,N] = A[M,K] @ B + bias (+gelu) (+resid)
//   BTRANS=false : B is [K,N] row-major (N multiple of 128 in all such calls)
//   BTRANS=true  : B is [N,K] row-major (logits: C = A @ B^T), N guarded
// Tiles: BM=128, BN=128, BK=8, 256 threads, 8x8 per thread.
// M is always a multiple of 128 here; K a multiple of 8.
// ---------------------------------------------------------------------------
template <bool BTRANS, bool GELU_ACT, bool RESID>
__global__ void sgemm_kernel(const float* __restrict__ A,
                             const float* __restrict__ B,
                             const float* __restrict__ bias,
                             const float* __restrict__ resid,
                             float* __restrict__ C,
                             int M, int N, int K) {
    const int BM = 128, BN = 128, BK = 8, TM = 8, TN = 8;
    __shared__ float As[BK][BM];
    __shared__ float Bs[BK][BN];

    const int tid = threadIdx.x;               // 0..255
    const int tx  = tid & 15;                  // 0..15
    const int ty  = tid >> 4;                  // 0..15
    const int m0  = blockIdx.y * BM;
    const int n0  = blockIdx.x * BN;

    float acc[TM][TN];
    #pragma unroll
    for (int i = 0; i < TM; i++)
        #pragma unroll
        for (int j = 0; j < TN; j++) acc[i][j] = 0.0f;

    // A loader: one float4 per thread; 256*4 = 1024 = BM*BK
    const int a_row = tid >> 1;                // 0..127
    const int a_col = (tid & 1) * 4;           // 0 or 4
    // B (non-trans) loader: 256*4 = 1024 = BK*BN
    const int b_row = tid >> 5;                // 0..7
    const int b_col = (tid & 31) * 4;          // 0..124
    // B (trans) loader: n index 0..127, k chunk 0 or 4
    const int bt_n  = tid >> 1;
    const int bt_k  = (tid & 1) * 4;

    for (int k0 = 0; k0 < K; k0 += BK) {
        float4 av = *(const float4*)(A + (size_t)(m0 + a_row) * K + k0 + a_col);
        As[a_col + 0][a_row] = av.x;
        As[a_col + 1][a_row] = av.y;
        As[a_col + 2][a_row] = av.z;
        As[a_col + 3][a_row] = av.w;

        if (!BTRANS) {
            float4 bv = *(const float4*)(B + (size_t)(k0 + b_row) * N + n0 + b_col);
            *(float4*)&Bs[b_row][b_col] = bv;
        } else {
            float4 bv = make_float4(0.f, 0.f, 0.f, 0.f);
            if (n0 + bt_n < N)
                bv = *(const float4*)(B + (size_t)(n0 + bt_n) * K + k0 + bt_k);
            Bs[bt_k + 0][bt_n] = bv.x;
            Bs[bt_k + 1][bt_n] = bv.y;
            Bs[bt_k + 2][bt_n] = bv.z;
            Bs[bt_k + 3][bt_n] = bv.w;
        }
        __syncthreads();

        #pragma unroll
        for (int kk = 0; kk < BK; kk++) {
            float ra[TM], rb[TN];
            #pragma unroll
            for (int i = 0; i < TM; i++) ra[i] = As[kk][ty * TM + i];
            #pragma unroll
            for (int j = 0; j < TN; j++) rb[j] = Bs[kk][tx * TN + j];
            #pragma unroll
            for (int i = 0; i < TM; i++)
                #pragma unroll
                for (int j = 0; j < TN; j++)
                    acc[i][j] = fmaf(ra[i], rb[j], acc[i][j]);
        }
        __syncthreads();
    }

    #pragma unroll
    for (int i = 0; i < TM; i++) {
        int m = m0 + ty * TM + i;
        #pragma unroll
        for (int j = 0; j < TN; j++) {
            int n = n0 + tx * TN + j;
            if (n < N) {
                float val = acc[i][j];
                if (bias) val += bias[n];
                if (GELU_ACT) val = gelu_exact(val);
                if (RESID) val += resid[(size_t)m * N + n];
                C[(size_t)m * N + n] = val;
            }
        }
    }
}

// ---------------------------------------------------------------------------
// Scores: P[b,h,s,t] = scale * dot(q[b,s,h,:], k[b,t,h,:]) for t<=s else NEG
// grid (S/64 t-tiles, S/64 s-tiles, B*H), block 256
// ---------------------------------------------------------------------------
__global__ void scores_kernel(const float* __restrict__ q,
                              const float* __restrict__ k,
                              float* __restrict__ p) {
    const int t0 = blockIdx.x * 64;
    const int s0 = blockIdx.y * 64;
    const int bh = blockIdx.z;
    const int b  = bh / H_;
    const int h  = bh % H_;
    const int tid = threadIdx.x;
    float* pout = p + (size_t)bh * S_ * S_;

    if (t0 >= s0 + 64) {   // fully masked tile
        for (int i = tid; i < 64 * 64; i += 256) {
            int si = i >> 6, ti = i & 63;
            pout[(size_t)(s0 + si) * S_ + t0 + ti] = NEGF;
        }
        return;
    }

    __shared__ float Qs[64][65];
    __shared__ float Ks[64][65];

    #pragma unroll
    for (int r = 0; r < 4; r++) {
        int idx = tid + 256 * r;            // 0..1023
        int row = idx >> 4;                 // 0..63
        int c   = (idx & 15) * 4;           // 0..60
        const float* qrow = q + ((size_t)(b * S_ + s0 + row) * H_ + h) * DK_;
        const float* krow = k + ((size_t)(b * S_ + t0 + row) * H_ + h) * DK_;
        float4 qv = *(const float4*)(qrow + c);
        float4 kv = *(const float4*)(krow + c);
        Qs[row][c + 0] = qv.x; Qs[row][c + 1] = qv.y;
        Qs[row][c + 2] = qv.z; Qs[row][c + 3] = qv.w;
        Ks[row][c + 0] = kv.x; Ks[row][c + 1] = kv.y;
        Ks[row][c + 2] = kv.z; Ks[row][c + 3] = kv.w;
    }
    __syncthreads();

    const int tx = tid & 15, ty = tid >> 4;
    float acc[4][4];
    #pragma unroll
    for (int i = 0; i < 4; i++)
        #pragma unroll
        for (int j = 0; j < 4; j++) acc[i][j] = 0.0f;

    #pragma unroll 8
    for (int kk = 0; kk < DK_; kk++) {
        float ra[4], rb[4];
        #pragma unroll
        for (int i = 0; i < 4; i++) ra[i] = Qs[ty * 4 + i][kk];
        #pragma unroll
        for (int j = 0; j < 4; j++) rb[j] = Ks[tx * 4 + j][kk];
        #pragma unroll
        for (int i = 0; i < 4; i++)
            #pragma unroll
            for (int j = 0; j < 4; j++)
                acc[i][j] = fmaf(ra[i], rb[j], acc[i][j]);
    }

    const float scale = 0.125f;  // 1/sqrt(64)
    #pragma unroll
    for (int i = 0; i < 4; i++) {
        int s = s0 + ty * 4 + i;
        #pragma unroll
        for (int j = 0; j < 4; j++) {
            int t = t0 + tx * 4 + j;
            pout[(size_t)s * S_ + t] = (t <= s) ? acc[i][j] * scale : NEGF;
        }
    }
}

// ---------------------------------------------------------------------------
// Row softmax over 1024 cols. grid (S, B*H), block 256.
// ---------------------------------------------------------------------------
__global__ void softmax_kernel(float* __restrict__ p) {
    float* pr = p + ((size_t)blockIdx.y * S_ + blockIdx.x) * S_;
    const int tid = threadIdx.x;
    __shared__ float red[256];

    float4 v = *(const float4*)(pr + tid * 4);
    float m = fmaxf(fmaxf(v.x, v.y), fmaxf(v.z, v.w));
    red[tid] = m;
    __syncthreads();
    for (int off = 128; off > 0; off >>= 1) {
        if (tid < off) red[tid] = fmaxf(red[tid], red[tid + off]);
        __syncthreads();
    }
    float mx = red[0];
    __syncthreads();

    float e0 = expf(v.x - mx), e1 = expf(v.y - mx);
    float e2 = expf(v.z - mx), e3 = expf(v.w - mx);
    red[tid] = e0 + e1 + e2 + e3;
    __syncthreads();
    for (int off = 128; off > 0; off >>= 1) {
        if (tid < off) red[tid] += red[tid + off];
        __syncthreads();
    }
    float inv = 1.0f / red[0];
    float4 o = make_float4(e0 * inv, e1 * inv, e2 * inv, e3 * inv);
    *(float4*)(pr + tid * 4) = o;
}

// ---------------------------------------------------------------------------
// AV: y[b,s,h,d] = sum_t P[b,h,s,t] * v[b,t,h,d]
// grid (S/64 s-tiles, B*H), block 256. Causal => only t < s0+64 contributes.
// ---------------------------------------------------------------------------
__global__ void av_kernel(const float* __restrict__ p,
                          const float* __restrict__ v,
                          float* __restrict__ y) {
    const int s0 = blockIdx.x * 64;
    const int bh = blockIdx.y;
    const int b  = bh / H_;
    const int h  = bh % H_;
    const int tid = threadIdx.x;
    const float* prow = p + (size_t)bh * S_ * S_;

    __shared__ float Ps[16][64];
    __shared__ float Vs[16][64];

    const int tx = tid & 15, ty = tid >> 4;
    float acc[4][4];
    #pragma unroll
    for (int i = 0; i < 4; i++)
        #pragma unroll
        for (int j = 0; j < 4; j++) acc[i][j] = 0.0f;

    const int kmax = s0 + 64;
    // loaders
    const int p_srow = tid >> 2;          // 0..63
    const int p_kc   = (tid & 3) * 4;     // 0..12
    const int v_kk   = tid >> 4;          // 0..15
    const int v_d    = (tid & 15) * 4;    // 0..60

    for (int k0 = 0; k0 < kmax; k0 += 16) {
        float4 pv = *(const float4*)(prow + (size_t)(s0 + p_srow) * S_ + k0 + p_kc);
        Ps[p_kc + 0][p_srow] = pv.x;
        Ps[p_kc + 1][p_srow] = pv.y;
        Ps[p_kc + 2][p_srow] = pv.z;
        Ps[p_kc + 3][p_srow] = pv.w;
        float4 vv = *(const float4*)(v + ((size_t)(b * S_ + k0 + v_kk) * H_ + h) * DK_ + v_d);
        *(float4*)&Vs[v_kk][v_d] = vv;
        __syncthreads();

        #pragma unroll
        for (int kk = 0; kk < 16; kk++) {
            float ra[4], rb[4];
            #pragma unroll
            for (int i = 0; i < 4; i++) ra[i] = Ps[kk][ty * 4 + i];
            #pragma unroll
            for (int j = 0; j < 4; j++) rb[j] = Vs[kk][tx * 4 + j];
            #pragma unroll
            for (int i = 0; i < 4; i++)
                #pragma unroll
                for (int j = 0; j < 4; j++)
                    acc[i][j] = fmaf(ra[i], rb[j], acc[i][j]);
        }
        __syncthreads();
    }

    #pragma unroll
    for (int i = 0; i < 4; i++) {
        int s = s0 + ty * 4 + i;
        #pragma unroll
        for (int j = 0; j < 4; j++) {
            int d = tx * 4 + j;
            y[((size_t)(b * S_ + s) * H_ + h) * DK_ + d] = acc[i][j];
        }
    }
}

// ---------------------------------------------------------------------------
// LayerNorm over last dim (1024). grid NTOK, block 256.
// ---------------------------------------------------------------------------
__global__ void layernorm_kernel(const float* __restrict__ x,
                                 const float* __restrict__ g,
                                 const float* __restrict__ bb,
                                 float* __restrict__ out) {
    const int row = blockIdx.x;
    const int tid = threadIdx.x;
    const float* xr = x + (size_t)row * D_;
    __shared__ float rs[256];
    __shared__ float rq[256];

    float4 v = *(const float4*)(xr + tid * 4);
    float s  = v.x + v.y + v.z + v.w;
    float sq = v.x * v.x + v.y * v.y + v.z * v.z + v.w * v.w;
    rs[tid] = s; rq[tid] = sq;
    __syncthreads();
    for (int off = 128; off > 0; off >>= 1) {
        if (tid < off) { rs[tid] += rs[tid + off]; rq[tid] += rq[tid + off]; }
        __syncthreads();
    }
    float mu  = rs[0] * (1.0f / D_);
    float var = rq[0] * (1.0f / D_) - mu * mu;
    float rstd = rsqrtf(var + 1e-5f);

    int c = tid * 4;
    float4 gv = *(const float4*)(g + c);
    float4 bv = *(const float4*)(bb + c);
    float4 o;
    o.x = (v.x - mu) * rstd * gv.x + bv.x;
    o.y = (v.y - mu) * rstd * gv.y + bv.y;
    o.z = (v.z - mu) * rstd * gv.z + bv.z;
    o.w = (v.w - mu) * rstd * gv.w + bv.w;
    *(float4*)(out + (size_t)row * D_ + c) = o;
}

// ---------------------------------------------------------------------------
// Host launcher
// ---------------------------------------------------------------------------
extern "C" void kernel_launch(void* const* d_in, const int* in_sizes, int n_in,
                              void* d_out, int out_size) {
    const int*   idx   = (const int*)  d_in[0];
    const float* te    = (const float*)d_in[1];
    const float* pe    = (const float*)d_in[2];
    const float* wq    = (const float*)d_in[3];
    const float* bq    = (const float*)d_in[4];
    const float* wk    = (const float*)d_in[5];
    const float* bk    = (const float*)d_in[6];
    const float* wv    = (const float*)d_in[7];
    const float* bv    = (const float*)d_in[8];
    const float* wo    = (const float*)d_in[9];
    const float* bo    = (const float*)d_in[10];
    const float* ln2g  = (const float*)d_in[11];
    const float* ln2b  = (const float*)d_in[12];
    const float* w1    = (const float*)d_in[13];
    const float* b1    = (const float*)d_in[14];
    const float* w2    = (const float*)d_in[15];
    const float* b2    = (const float*)d_in[16];
    const float* lnfg  = (const float*)d_in[17];
    const float* lnfb  = (const float*)d_in[18];
    float* out = (float*)d_out;

    float *x, *q, *k, *v, *y, *ln, *h1, *p;
    cudaGetSymbolAddress((void**)&x,  g_x);
    cudaGetSymbolAddress((void**)&q,  g_q);
    cudaGetSymbolAddress((void**)&k,  g_k);
    cudaGetSymbolAddress((void**)&v,  g_v);
    cudaGetSymbolAddress((void**)&y,  g_y);
    cudaGetSymbolAddress((void**)&ln, g_ln);
    cudaGetSymbolAddress((void**)&h1, g_h1);
    cudaGetSymbolAddress((void**)&p,  g_p);

    embed_kernel<<<NTOK, 256>>>(idx, te, pe, x);

    const dim3 gD(D_ / 128, NTOK / 128);        // (8, 16)
    const dim3 gF(DFF_ / 128, NTOK / 128);      // (32, 16)
    const dim3 gScore(S_ / 64, S_ / 64, B_ * H_);
    const dim3 gSoft(S_, B_ * H_);
    const dim3 gAV(S_ / 64, B_ * H_);

    for (int l = 0; l < L_; l++) {
        const float* wq_l = wq + (size_t)l * D_ * D_;
        const float* wk_l = wk + (size_t)l * D_ * D_;
        const float* wv_l = wv + (size_t)l * D_ * D_;
        const float* wo_l = wo + (size_t)l * D_ * D_;
        const float* w1_l = w1 + (size_t)l * D_ * DFF_;
        const float* w2_l = w2 + (size_t)l * DFF_ * D_;

        sgemm_kernel<false, false, false><<<gD, 256>>>(x, wq_l, bq + l * D_, nullptr, q, NTOK, D_, D_);
        sgemm_kernel<false, false, false><<<gD, 256>>>(x, wk_l, bk + l * D_, nullptr, k, NTOK, D_, D_);
        sgemm_kernel<false, false, false><<<gD, 256>>>(x, wv_l, bv + l * D_, nullptr, v, NTOK, D_, D_);

        scores_kernel<<<gScore, 256>>>(q, k, p);
        softmax_kernel<<<gSoft, 256>>>(p);
        av_kernel<<<gAV, 256>>>(p, v, y);

        // x = x + (y @ wo + bo)
        sgemm_kernel<false, false, true><<<gD, 256>>>(y, wo_l, bo + l * D_, x, x, NTOK, D_, D_);
        // h = LN(x)
        layernorm_kernel<<<NTOK, 256>>>(x, ln2g + l * D_, ln2b + l * D_, ln);
        // h1 = gelu(h @ w1 + b1)
        sgemm_kernel<false, true, false><<<gF, 256>>>(ln, w1_l, b1 + l * DFF_, nullptr, h1, NTOK, DFF_, D_);
        // x = x + (h1 @ w2 + b2)
        sgemm_kernel<false, false, true><<<gD, 256>>>(h1, w2_l, b2 + l * D_, x, x, NTOK, D_, DFF_);
    }

    layernorm_kernel<<<NTOK, 256>>>(x, lnfg, lnfb, ln);

    const dim3 gLogits((V_ + 127) / 128, NTOK / 128);   // (393, 16)
    sgemm_kernel<true, false, false><<<gLogits, 256>>>(ln, te, nullptr, nullptr, out, NTOK, V_, D_);
}

// round 2
// speedup vs baseline: 2.0937x; 2.0937x over previous
#include <cuda_runtime.h>
#include <cuda_bf16.h>
#include <math.h>

#define D_   1024
#define H_   16
#define V_   50257
#define L_   4
#define B_   2
#define S_   1024
#define DK_  64
#define DFF_ 4096
#define NTOK (B_ * S_)
#define NEGF (-3.402823466e38f)

// ---------------------------------------------------------------------------
// Device scratch
// ---------------------------------------------------------------------------
__device__ float g_x [NTOK * D_];
__device__ float g_q [NTOK * D_];
__device__ float g_k [NTOK * D_];
__device__ float g_v [NTOK * D_];
__device__ float g_y [NTOK * D_];
__device__ float g_ln[NTOK * D_];
__device__ float g_h1[NTOK * DFF_];
__device__ float g_p [(size_t)B_ * H_ * S_ * S_];

__device__ __forceinline__ float gelu_exact(float v) {
    return 0.5f * v * (1.0f + erff(v * 0.70710678118654752440f));
}

__device__ __forceinline__ unsigned f2tf32(float x) {
    unsigned u;
    asm("cvt.rna.tf32.f32 %0, %1;" : "=r"(u) : "f"(x));
    return u;
}

__device__ __forceinline__ void mma_tf32(float* c, const unsigned* a, const unsigned* b) {
    asm volatile(
        "mma.sync.aligned.m16n8k8.row.col.f32.tf32.tf32.f32 "
        "{%0,%1,%2,%3},{%4,%5,%6,%7},{%8,%9},{%0,%1,%2,%3};"
        : "+f"(c[0]), "+f"(c[1]), "+f"(c[2]), "+f"(c[3])
        : "r"(a[0]), "r"(a[1]), "r"(a[2]), "r"(a[3]), "r"(b[0]), "r"(b[1]));
}

// ---------------------------------------------------------------------------
// Embedding
// ---------------------------------------------------------------------------
__global__ void embed_kernel(const int* __restrict__ idx,
                             const float* __restrict__ te,
                             const float* __restrict__ pe,
                             float* __restrict__ x) {
    int row = blockIdx.x;
    int s   = row % S_;
    int tok = idx[row];
    int c   = threadIdx.x * 4;
    float4 t = *(const float4*)(te + (size_t)tok * D_ + c);
    float4 p = *(const float4*)(pe + (size_t)s   * D_ + c);
    *(float4*)(x + (size_t)row * D_ + c) =
        make_float4(t.x + p.x, t.y + p.y, t.z + p.z, t.w + p.w);
}

// ---------------------------------------------------------------------------
// Generic TF32 MMA GEMM.
//   C[M,N] (+ z-batched) = A[M,K] @ B (+ bias) (+gelu) (+resid) (+scale/mask)
//   BTRANS: B stored [N,K] row-major (logits: te; scores: k)
//   SMASK : causal mask + 1/8 scale epilogue (scores)
//   NGUARD: guard n against N (logits, N=50257)
//   CAUSALK: cap K loop at m0+BM (AV; masked P entries are exactly 0)
//   z-batching: offsets = (z/zdiv)*s1 + (z%zdiv)*s2 for A,B,C.
// Tiles: BM=128, BN in {128,64}, BK=16, 256 threads, 8 warps.
// ---------------------------------------------------------------------------
template <int BN, bool BTRANS, bool GELU_ACT, bool RESID, bool SMASK,
          bool NGUARD, bool CAUSALK>
__global__ void __launch_bounds__(256, 2)
mma_gemm(const float* __restrict__ Ag, const float* __restrict__ Bg,
         const float* __restrict__ bias, const float* __restrict__ resid,
         float* __restrict__ Cg,
         int M, int N, int K, int lda, int ldb, int ldc,
         int zdiv, long long za1, long long za2, long long zb1, long long zb2,
         long long zc1, long long zc2)
{
    constexpr int BM = 128, BK = 16;
    constexpr int ASTR = 20;             // As row stride (conflict-free frags)
    constexpr int BSTR = BN + 4;         // Bs row stride
    constexpr int WN   = (BN == 128) ? 2 : 1;
    constexpr int WMC  = 8 / WN;         // warps along M
    constexpr int WROWS = BM / WMC;      // 32 or 16
    constexpr int MT   = WROWS / 16;     // 2 or 1
    constexpr int NT   = (BN / WN) / 8;  // 8

    __shared__ float As[BM * ASTR];
    __shared__ float Bs[BK * BSTR];

    const int tid  = threadIdx.x;
    const int wid  = tid >> 5;
    const int lane = tid & 31;
    const int g    = lane >> 2;
    const int tq   = lane & 3;
    const int m0   = blockIdx.y * BM;
    const int n0   = blockIdx.x * BN;
    const int z    = blockIdx.z;

    const float* A = Ag + (long long)(z / zdiv) * za1 + (long long)(z % zdiv) * za2;
    const float* B = Bg + (long long)(z / zdiv) * zb1 + (long long)(z % zdiv) * zb2;
    float*       C = Cg + (long long)(z / zdiv) * zc1 + (long long)(z % zdiv) * zc2;

    if (SMASK && n0 >= m0 + BM) {        // fully masked scores tile
        for (int i = tid; i < BM * BN; i += 256) {
            int r = i / BN, c = i % BN;
            C[(long long)(m0 + r) * ldc + n0 + c] = NEGF;
        }
        return;
    }

    const int rowbase = (wid % WMC) * WROWS;
    const int colbase = (wid / WMC) * (BN / WN);

    float acc[MT][NT][4];
    #pragma unroll
    for (int i = 0; i < MT; i++)
        #pragma unroll
        for (int j = 0; j < NT; j++)
            #pragma unroll
            for (int q = 0; q < 4; q++) acc[i][j][q] = 0.0f;

    int kend = K;
    if (CAUSALK) { int cap = m0 + BM; kend = (K < cap) ? K : cap; }

    // loader indices
    const int ar = tid >> 1, ac = (tid & 1) * 8;          // A: 2 x float4
    const int bk = tid >> 4;                               // B non-trans row
    const int tn = tid >> 1, tk = (tid & 1) * 8;          // B trans

    for (int k0 = 0; k0 < kend; k0 += BK) {
        // ---- A tile -> As[m][k] (tf32) ----
        {
            const float* src = A + (long long)(m0 + ar) * lda + k0 + ac;
            float4 v0 = *(const float4*)src;
            float4 v1 = *(const float4*)(src + 4);
            float4 w0, w1;
            w0.x = __uint_as_float(f2tf32(v0.x)); w0.y = __uint_as_float(f2tf32(v0.y));
            w0.z = __uint_as_float(f2tf32(v0.z)); w0.w = __uint_as_float(f2tf32(v0.w));
            w1.x = __uint_as_float(f2tf32(v1.x)); w1.y = __uint_as_float(f2tf32(v1.y));
            w1.z = __uint_as_float(f2tf32(v1.z)); w1.w = __uint_as_float(f2tf32(v1.w));
            *(float4*)&As[ar * ASTR + ac]     = w0;
            *(float4*)&As[ar * ASTR + ac + 4] = w1;
        }
        // ---- B tile -> Bs[k][n] (tf32) ----
        if (!BTRANS) {
            if (BN == 128) {
                const int bc = (tid & 15) * 8;
                const float* src = B + (long long)(k0 + bk) * ldb + n0 + bc;
                float4 v0 = *(const float4*)src;
                float4 v1 = *(const float4*)(src + 4);
                float4 w0, w1;
                w0.x = __uint_as_float(f2tf32(v0.x)); w0.y = __uint_as_float(f2tf32(v0.y));
                w0.z = __uint_as_float(f2tf32(v0.z)); w0.w = __uint_as_float(f2tf32(v0.w));
                w1.x = __uint_as_float(f2tf32(v1.x)); w1.y = __uint_as_float(f2tf32(v1.y));
                w1.z = __uint_as_float(f2tf32(v1.z)); w1.w = __uint_as_float(f2tf32(v1.w));
                *(float4*)&Bs[bk * BSTR + bc]     = w0;
                *(float4*)&Bs[bk * BSTR + bc + 4] = w1;
            } else {
                const int bc = (tid & 15) * 4;
                const float* src = B + (long long)(k0 + bk) * ldb + n0 + bc;
                float4 v0 = *(const float4*)src;
                float4 w0;
                w0.x = __uint_as_float(f2tf32(v0.x)); w0.y = __uint_as_float(f2tf32(v0.y));
                w0.z = __uint_as_float(f2tf32(v0.z)); w0.w = __uint_as_float(f2tf32(v0.w));
                *(float4*)&Bs[bk * BSTR + bc] = w0;
            }
        } else {
            // B is [N,K] row-major; transpose into Bs[k][n]
            float4 v0 = make_float4(0.f, 0.f, 0.f, 0.f);
            float4 v1 = make_float4(0.f, 0.f, 0.f, 0.f);
            bool ok = true;
            if (NGUARD) ok = (n0 + tn) < N;
            if (ok) {
                const float* src = B + (long long)(n0 + tn) * ldb + k0 + tk;
                v0 = *(const float4*)src;
                v1 = *(const float4*)(src + 4);
            }
            Bs[(tk + 0) * BSTR + tn] = __uint_as_float(f2tf32(v0.x));
            Bs[(tk + 1) * BSTR + tn] = __uint_as_float(f2tf32(v0.y));
            Bs[(tk + 2) * BSTR + tn] = __uint_as_float(f2tf32(v0.z));
            Bs[(tk + 3) * BSTR + tn] = __uint_as_float(f2tf32(v0.w));
            Bs[(tk + 4) * BSTR + tn] = __uint_as_float(f2tf32(v1.x));
            Bs[(tk + 5) * BSTR + tn] = __uint_as_float(f2tf32(v1.y));
            Bs[(tk + 6) * BSTR + tn] = __uint_as_float(f2tf32(v1.z));
            Bs[(tk + 7) * BSTR + tn] = __uint_as_float(f2tf32(v1.w));
        }
        __syncthreads();

        #pragma unroll
        for (int ks = 0; ks < BK; ks += 8) {
            unsigned af[MT][4];
            #pragma unroll
            for (int i = 0; i < MT; i++) {
                int r = rowbase + i * 16 + g;
                af[i][0] = __float_as_uint(As[r * ASTR + ks + tq]);
                af[i][1] = __float_as_uint(As[(r + 8) * ASTR + ks + tq]);
                af[i][2] = __float_as_uint(As[r * ASTR + ks + tq + 4]);
                af[i][3] = __float_as_uint(As[(r + 8) * ASTR + ks + tq + 4]);
            }
            unsigned bf[NT][2];
            #pragma unroll
            for (int j = 0; j < NT; j++) {
                int c = colbase + j * 8 + g;
                bf[j][0] = __float_as_uint(Bs[(ks + tq) * BSTR + c]);
                bf[j][1] = __float_as_uint(Bs[(ks + tq + 4) * BSTR + c]);
            }
            #pragma unroll
            for (int i = 0; i < MT; i++)
                #pragma unroll
                for (int j = 0; j < NT; j++)
                    mma_tf32(acc[i][j], af[i], bf[j]);
        }
        __syncthreads();
    }

    // ---- epilogue ----
    #pragma unroll
    for (int i = 0; i < MT; i++) {
        #pragma unroll
        for (int j = 0; j < NT; j++) {
            int r = m0 + rowbase + i * 16 + g;
            int c = n0 + colbase + j * 8 + tq * 2;
            #pragma unroll
            for (int q = 0; q < 4; q++) {
                int rr = r + (q >> 1) * 8;
                int cc = c + (q & 1);
                if (NGUARD && cc >= N) continue;
                float val = acc[i][j][q];
                if (bias) val += bias[cc];
                if (GELU_ACT) val = gelu_exact(val);
                if (RESID) val += resid[(long long)rr * ldc + cc];
                if (SMASK) val = (cc <= rr) ? val * 0.125f : NEGF;
                C[(long long)rr * ldc + cc] = val;
            }
        }
    }
}

// ---------------------------------------------------------------------------
// Row softmax over 1024 cols. grid (S, B*H), block 256.
// ---------------------------------------------------------------------------
__global__ void softmax_kernel(float* __restrict__ p) {
    float* pr = p + ((size_t)blockIdx.y * S_ + blockIdx.x) * S_;
    const int tid = threadIdx.x;
    __shared__ float red[256];

    float4 v = *(const float4*)(pr + tid * 4);
    float m = fmaxf(fmaxf(v.x, v.y), fmaxf(v.z, v.w));
    red[tid] = m;
    __syncthreads();
    for (int off = 128; off > 0; off >>= 1) {
        if (tid < off) red[tid] = fmaxf(red[tid], red[tid + off]);
        __syncthreads();
    }
    float mx = red[0];
    __syncthreads();

    float e0 = expf(v.x - mx), e1 = expf(v.y - mx);
    float e2 = expf(v.z - mx), e3 = expf(v.w - mx);
    red[tid] = e0 + e1 + e2 + e3;
    __syncthreads();
    for (int off = 128; off > 0; off >>= 1) {
        if (tid < off) red[tid] += red[tid + off];
        __syncthreads();
    }
    float inv = 1.0f / red[0];
    *(float4*)(pr + tid * 4) = make_float4(e0 * inv, e1 * inv, e2 * inv, e3 * inv);
}

// ---------------------------------------------------------------------------
// LayerNorm over last dim (1024). grid NTOK, block 256.
// ---------------------------------------------------------------------------
__global__ void layernorm_kernel(const float* __restrict__ x,
                                 const float* __restrict__ g,
                                 const float* __restrict__ bb,
                                 float* __restrict__ out) {
    const int row = blockIdx.x;
    const int tid = threadIdx.x;
    const float* xr = x + (size_t)row * D_;
    __shared__ float rs[256];
    __shared__ float rq[256];

    float4 v = *(const float4*)(xr + tid * 4);
    float s  = v.x + v.y + v.z + v.w;
    float sq = v.x * v.x + v.y * v.y + v.z * v.z + v.w * v.w;
    rs[tid] = s; rq[tid] = sq;
    __syncthreads();
    for (int off = 128; off > 0; off >>= 1) {
        if (tid < off) { rs[tid] += rs[tid + off]; rq[tid] += rq[tid + off]; }
        __syncthreads();
    }
    float mu  = rs[0] * (1.0f / D_);
    float var = rq[0] * (1.0f / D_) - mu * mu;
    float rstd = rsqrtf(var + 1e-5f);

    int c = tid * 4;
    float4 gv = *(const float4*)(g + c);
    float4 bv = *(const float4*)(bb + c);
    float4 o;
    o.x = (v.x - mu) * rstd * gv.x + bv.x;
    o.y = (v.y - mu) * rstd * gv.y + bv.y;
    o.z = (v.z - mu) * rstd * gv.z + bv.z;
    o.w = (v.w - mu) * rstd * gv.w + bv.w;
    *(float4*)(out + (size_t)row * D_ + c) = o;
}

// ---------------------------------------------------------------------------
// Host launcher
// ---------------------------------------------------------------------------
extern "C" void kernel_launch(void* const* d_in, const int* in_sizes, int n_in,
                              void* d_out, int out_size) {
    const int*   idx   = (const int*)  d_in[0];
    const float* te    = (const float*)d_in[1];
    const float* pe    = (const float*)d_in[2];
    const float* wq    = (const float*)d_in[3];
    const float* bq    = (const float*)d_in[4];
    const float* wk    = (const float*)d_in[5];
    const float* bk    = (const float*)d_in[6];
    const float* wv    = (const float*)d_in[7];
    const float* bv    = (const float*)d_in[8];
    const float* wo    = (const float*)d_in[9];
    const float* bo    = (const float*)d_in[10];
    const float* ln2g  = (const float*)d_in[11];
    const float* ln2b  = (const float*)d_in[12];
    const float* w1    = (const float*)d_in[13];
    const float* b1    = (const float*)d_in[14];
    const float* w2    = (const float*)d_in[15];
    const float* b2    = (const float*)d_in[16];
    const float* lnfg  = (const float*)d_in[17];
    const float* lnfb  = (const float*)d_in[18];
    float* out = (float*)d_out;

    float *x, *q, *k, *v, *y, *ln, *h1, *p;
    cudaGetSymbolAddress((void**)&x,  g_x);
    cudaGetSymbolAddress((void**)&q,  g_q);
    cudaGetSymbolAddress((void**)&k,  g_k);
    cudaGetSymbolAddress((void**)&v,  g_v);
    cudaGetSymbolAddress((void**)&y,  g_y);
    cudaGetSymbolAddress((void**)&ln, g_ln);
    cudaGetSymbolAddress((void**)&h1, g_h1);
    cudaGetSymbolAddress((void**)&p,  g_p);

    embed_kernel<<<NTOK, 256>>>(idx, te, pe, x);

    const dim3 gD(D_ / 128, NTOK / 128);          // (8, 16)
    const dim3 gF(DFF_ / 128, NTOK / 128);        // (32, 16)
    const dim3 gSc(S_ / 128, S_ / 128, B_ * H_);  // (8, 8, 32)
    const dim3 gAv(1, S_ / 128, B_ * H_);         // (1, 8, 32)
    const dim3 gSm(S_, B_ * H_);
    const dim3 gLg((V_ + 127) / 128, NTOK / 128); // (393, 16)

    const long long SD = (long long)S_ * D_;
    const long long SS = (long long)S_ * S_;

    for (int l = 0; l < L_; l++) {
        const float* wq_l = wq + (size_t)l * D_ * D_;
        const float* wk_l = wk + (size_t)l * D_ * D_;
        const float* wv_l = wv + (size_t)l * D_ * D_;
        const float* wo_l = wo + (size_t)l * D_ * D_;
        const float* w1_l = w1 + (size_t)l * D_ * DFF_;
        const float* w2_l = w2 + (size_t)l * DFF_ * D_;

        // q/k/v = x @ W + b
        mma_gemm<128,false,false,false,false,false,false><<<gD, 256>>>(
            x, wq_l, bq + l * D_, nullptr, q, NTOK, D_, D_, D_, D_, D_,
            1, 0,0, 0,0, 0,0);
        mma_gemm<128,false,false,false,false,false,false><<<gD, 256>>>(
            x, wk_l, bk + l * D_, nullptr, k, NTOK, D_, D_, D_, D_, D_,
            1, 0,0, 0,0, 0,0);
        mma_gemm<128,false,false,false,false,false,false><<<gD, 256>>>(
            x, wv_l, bv + l * D_, nullptr, v, NTOK, D_, D_, D_, D_, D_,
            1, 0,0, 0,0, 0,0);

        // P = mask(scale(q @ k^T)) per (b,h)
        mma_gemm<128,true,false,false,true,false,false><<<gSc, 256>>>(
            q, k, nullptr, nullptr, p, S_, S_, DK_, D_, D_, S_,
            H_, SD, 64, SD, 64, 16 * SS, SS);

        softmax_kernel<<<gSm, 256>>>(p);

        // y = P @ v per (b,h)
        mma_gemm<64,false,false,false,false,false,true><<<gAv, 256>>>(
            p, v, nullptr, nullptr, y, S_, DK_, S_, S_, D_, D_,
            H_, 16 * SS, SS, SD, 64, SD, 64);

        // x = x + (y @ wo + bo)
        mma_gemm<128,false,false,true,false,false,false><<<gD, 256>>>(
            y, wo_l, bo + l * D_, x, x, NTOK, D_, D_, D_, D_, D_,
            1, 0,0, 0,0, 0,0);

        layernorm_kernel<<<NTOK, 256>>>(x, ln2g + l * D_, ln2b + l * D_, ln);

        // h1 = gelu(ln @ w1 + b1)
        mma_gemm<128,false,true,false,false,false,false><<<gF, 256>>>(
            ln, w1_l, b1 + l * DFF_, nullptr, h1, NTOK, DFF_, D_, D_, DFF_, DFF_,
            1, 0,0, 0,0, 0,0);

        // x = x + (h1 @ w2 + b2)
        mma_gemm<128,false,false,true,false,false,false><<<gD, 256>>>(
            h1, w2_l, b2 + l * D_, x, x, NTOK, D_, DFF_, DFF_, D_, D_,
            1, 0,0, 0,0, 0,0);
    }

    layernorm_kernel<<<NTOK, 256>>>(x, lnfg, lnfb, ln);

    // logits = ln @ te^T
    mma_gemm<128,true,false,false,false,true,false><<<gLg, 256>>>(
        ln, te, nullptr, nullptr, out, NTOK, V_, D_, D_, D_, V_,
        1, 0,0, 0,0, 0,0);
}

// round 3
// speedup vs baseline: 2.8014x; 1.3380x over previous
#include <cuda_runtime.h>
#include <cuda_bf16.h>
#include <math.h>

#define D_   1024
#define H_   16
#define V_   50257
#define L_   4
#define B_   2
#define S_   1024
#define DK_  64
#define DFF_ 4096
#define NTOK (B_ * S_)
#define NEGF (-3.402823466e38f)

// ---------------------------------------------------------------------------
// Device scratch
// ---------------------------------------------------------------------------
__device__ float g_x [NTOK * D_];
__device__ float g_q [NTOK * D_];
__device__ float g_k [NTOK * D_];
__device__ float g_v [NTOK * D_];
__device__ float g_y [NTOK * D_];
__device__ float g_ln[NTOK * D_];
__device__ float g_h1[NTOK * DFF_];
__device__ float g_p [(size_t)B_ * H_ * S_ * S_];   // attention P / split-K partials

__device__ __forceinline__ float gelu_exact(float v) {
    return 0.5f * v * (1.0f + erff(v * 0.70710678118654752440f));
}

__device__ __forceinline__ unsigned f2tf32(float x) {
    unsigned u;
    asm("cvt.rna.tf32.f32 %0, %1;" : "=r"(u) : "f"(x));
    return u;
}
__device__ __forceinline__ float f2tf32f(float x) { return __uint_as_float(f2tf32(x)); }

__device__ __forceinline__ void mma_tf32(float* c, const unsigned* a, const unsigned* b) {
    asm volatile(
        "mma.sync.aligned.m16n8k8.row.col.f32.tf32.tf32.f32 "
        "{%0,%1,%2,%3},{%4,%5,%6,%7},{%8,%9},{%0,%1,%2,%3};"
        : "+f"(c[0]), "+f"(c[1]), "+f"(c[2]), "+f"(c[3])
        : "r"(a[0]), "r"(a[1]), "r"(a[2]), "r"(a[3]), "r"(b[0]), "r"(b[1]));
}

// ---------------------------------------------------------------------------
// Embedding
// ---------------------------------------------------------------------------
__global__ void embed_kernel(const int* __restrict__ idx,
                             const float* __restrict__ te,
                             const float* __restrict__ pe,
                             float* __restrict__ x) {
    int row = blockIdx.x;
    int s   = row % S_;
    int tok = idx[row];
    int c   = threadIdx.x * 4;
    float4 t = *(const float4*)(te + (size_t)tok * D_ + c);
    float4 p = *(const float4*)(pe + (size_t)s   * D_ + c);
    *(float4*)(x + (size_t)row * D_ + c) =
        make_float4(t.x + p.x, t.y + p.y, t.z + p.z, t.w + p.w);
}

// ---------------------------------------------------------------------------
// TF32 MMA GEMM, double-buffered.
//   BTRANS : B stored [N,K] row-major (scores: k; logits: te)
//   SMASK  : causal mask + 1/8 scale epilogue (scores)
//   NGUARD : guard n against N (logits)
//   CAUSALK: cap K loop at m0+BM (AV)
//   QKV    : blockIdx.z in {0,1,2} selects (B,bias,C) triple
//   SPLITK : z partitions K; partial slabs written to C + z*M*ldc, raw store
// Tiles: BM=128, BN in {128,64}, BK=16, 256 threads, 8 warps.
// ---------------------------------------------------------------------------
template <int BN, bool BTRANS, bool GELU_ACT, bool RESID, bool SMASK,
          bool NGUARD, bool CAUSALK, bool QKV, int SPLITK>
__global__ void __launch_bounds__(256, 2)
mma_gemm(const float* __restrict__ Ag, const float* __restrict__ Bg,
         const float* __restrict__ biasg, const float* __restrict__ resid,
         float* __restrict__ Cg,
         int M, int N, int K, int lda, int ldb, int ldc,
         int zdiv, long long za1, long long za2, long long zb1, long long zb2,
         long long zc1, long long zc2,
         const float* Bg2, const float* bias2, float* Cg2,
         const float* Bg3, const float* bias3, float* Cg3)
{
    constexpr int BM = 128, BK = 16;
    constexpr int ASTR = 20;
    constexpr int BSTR = BN + 8;
    constexpr int WN   = (BN == 128) ? 2 : 1;
    constexpr int WMC  = 8 / WN;
    constexpr int WROWS = BM / WMC;
    constexpr int MT   = WROWS / 16;
    constexpr int NT   = (BN / WN) / 8;

    __shared__ float As[2 * BM * ASTR];
    __shared__ float Bs[2 * BK * BSTR];

    const int tid  = threadIdx.x;
    const int wid  = tid >> 5;
    const int lane = tid & 31;
    const int g    = lane >> 2;
    const int tq   = lane & 3;
    const int m0   = blockIdx.y * BM;
    const int n0   = blockIdx.x * BN;
    const int z    = blockIdx.z;

    const float* A = Ag;
    const float* B = Bg;
    const float* bias = biasg;
    float* C = Cg;

    if (QKV) {
        if (z == 1) { B = Bg2; bias = bias2; C = Cg2; }
        else if (z == 2) { B = Bg3; bias = bias3; C = Cg3; }
    } else if (SPLITK > 1) {
        C = Cg + (long long)z * M * ldc;
    } else {
        A += (long long)(z / zdiv) * za1 + (long long)(z % zdiv) * za2;
        B += (long long)(z / zdiv) * zb1 + (long long)(z % zdiv) * zb2;
        C += (long long)(z / zdiv) * zc1 + (long long)(z % zdiv) * zc2;
    }

    if (SMASK && n0 >= m0 + BM) {
        for (int i = tid; i < BM * BN; i += 256) {
            int r = i / BN, c = i % BN;
            C[(long long)(m0 + r) * ldc + n0 + c] = NEGF;
        }
        return;
    }

    const int rowbase = (wid % WMC) * WROWS;
    const int colbase = (wid / WMC) * (BN / WN);

    float acc[MT][NT][4];
    #pragma unroll
    for (int i = 0; i < MT; i++)
        #pragma unroll
        for (int j = 0; j < NT; j++)
            #pragma unroll
            for (int q = 0; q < 4; q++) acc[i][j][q] = 0.0f;

    int kbeg = 0;
    int kend = K;
    if (SPLITK > 1) { kbeg = z * (K / SPLITK); kend = kbeg + K / SPLITK; }
    if (CAUSALK) { int cap = m0 + BM; if (cap < kend) kend = cap; }
    const int ntiles = (kend - kbeg) / BK;

    // loader indices
    const int ar = tid >> 1, ac = (tid & 1) * 8;      // A
    const int bk = tid >> 4;                          // B non-trans
    const int bc128 = (tid & 15) * 8;
    const int bc64  = (tid & 15) * 4;
    const int tn = tid >> 1, tk = (tid & 1) * 8;      // B trans

    auto ldg_tile = [&](int k0, float4& a0, float4& a1, float4& b0, float4& b1) {
        const float* srcA = A + (long long)(m0 + ar) * lda + k0 + ac;
        a0 = *(const float4*)srcA;
        a1 = *(const float4*)(srcA + 4);
        if (!BTRANS) {
            const float* srcB = B + (long long)(k0 + bk) * ldb + n0 + ((BN == 128) ? bc128 : bc64);
            b0 = *(const float4*)srcB;
            if (BN == 128) b1 = *(const float4*)(srcB + 4);
        } else {
            b0 = make_float4(0.f, 0.f, 0.f, 0.f);
            b1 = make_float4(0.f, 0.f, 0.f, 0.f);
            bool ok = !NGUARD || (n0 + tn) < N;
            if (ok) {
                const float* srcB = B + (long long)(n0 + tn) * ldb + k0 + tk;
                b0 = *(const float4*)srcB;
                b1 = *(const float4*)(srcB + 4);
            }
        }
    };

    auto sts_tile = [&](int buf, float4 a0, float4 a1, float4 b0, float4 b1) {
        float* as = As + buf * BM * ASTR;
        float* bs = Bs + buf * BK * BSTR;
        float4 w0, w1;
        w0.x = f2tf32f(a0.x); w0.y = f2tf32f(a0.y); w0.z = f2tf32f(a0.z); w0.w = f2tf32f(a0.w);
        w1.x = f2tf32f(a1.x); w1.y = f2tf32f(a1.y); w1.z = f2tf32f(a1.z); w1.w = f2tf32f(a1.w);
        *(float4*)&as[ar * ASTR + ac]     = w0;
        *(float4*)&as[ar * ASTR + ac + 4] = w1;
        if (!BTRANS) {
            float4 u0, u1;
            u0.x = f2tf32f(b0.x); u0.y = f2tf32f(b0.y); u0.z = f2tf32f(b0.z); u0.w = f2tf32f(b0.w);
            if (BN == 128) {
                u1.x = f2tf32f(b1.x); u1.y = f2tf32f(b1.y); u1.z = f2tf32f(b1.z); u1.w = f2tf32f(b1.w);
                *(float4*)&bs[bk * BSTR + bc128]     = u0;
                *(float4*)&bs[bk * BSTR + bc128 + 4] = u1;
            } else {
                *(float4*)&bs[bk * BSTR + bc64] = u0;
            }
        } else {
            bs[(tk + 0) * BSTR + tn] = f2tf32f(b0.x);
            bs[(tk + 1) * BSTR + tn] = f2tf32f(b0.y);
            bs[(tk + 2) * BSTR + tn] = f2tf32f(b0.z);
            bs[(tk + 3) * BSTR + tn] = f2tf32f(b0.w);
            bs[(tk + 4) * BSTR + tn] = f2tf32f(b1.x);
            bs[(tk + 5) * BSTR + tn] = f2tf32f(b1.y);
            bs[(tk + 6) * BSTR + tn] = f2tf32f(b1.z);
            bs[(tk + 7) * BSTR + tn] = f2tf32f(b1.w);
        }
    };

    // prologue
    {
        float4 a0, a1, b0, b1;
        ldg_tile(kbeg, a0, a1, b0, b1);
        sts_tile(0, a0, a1, b0, b1);
    }
    __syncthreads();

    for (int t = 0; t < ntiles; t++) {
        const int cur = t & 1;
        const bool has_next = (t + 1) < ntiles;
        float4 a0, a1, b0, b1;
        if (has_next) ldg_tile(kbeg + (t + 1) * BK, a0, a1, b0, b1);

        const float* as = As + cur * BM * ASTR;
        const float* bs = Bs + cur * BK * BSTR;
        #pragma unroll
        for (int ks = 0; ks < BK; ks += 8) {
            unsigned af[MT][4];
            #pragma unroll
            for (int i = 0; i < MT; i++) {
                int r = rowbase + i * 16 + g;
                af[i][0] = __float_as_uint(as[r * ASTR + ks + tq]);
                af[i][1] = __float_as_uint(as[(r + 8) * ASTR + ks + tq]);
                af[i][2] = __float_as_uint(as[r * ASTR + ks + tq + 4]);
                af[i][3] = __float_as_uint(as[(r + 8) * ASTR + ks + tq + 4]);
            }
            unsigned bf[NT][2];
            #pragma unroll
            for (int j = 0; j < NT; j++) {
                int c = colbase + j * 8 + g;
                bf[j][0] = __float_as_uint(bs[(ks + tq) * BSTR + c]);
                bf[j][1] = __float_as_uint(bs[(ks + tq + 4) * BSTR + c]);
            }
            #pragma unroll
            for (int i = 0; i < MT; i++)
                #pragma unroll
                for (int j = 0; j < NT; j++)
                    mma_tf32(acc[i][j], af[i], bf[j]);
        }

        if (has_next) sts_tile(cur ^ 1, a0, a1, b0, b1);
        __syncthreads();
    }

    // ---- epilogue ----
    #pragma unroll
    for (int i = 0; i < MT; i++) {
        #pragma unroll
        for (int j = 0; j < NT; j++) {
            int r = m0 + rowbase + i * 16 + g;
            int c = n0 + colbase + j * 8 + tq * 2;
            #pragma unroll
            for (int q = 0; q < 4; q++) {
                int rr = r + (q >> 1) * 8;
                int cc = c + (q & 1);
                if (NGUARD && cc >= N) continue;
                float val = acc[i][j][q];
                if (SPLITK > 1) {
                    C[(long long)rr * ldc + cc] = val;
                } else {
                    if (bias) val += bias[cc];
                    if (GELU_ACT) val = gelu_exact(val);
                    if (RESID) val += resid[(long long)rr * ldc + cc];
                    if (SMASK) val = (cc <= rr) ? val * 0.125f : NEGF;
                    C[(long long)rr * ldc + cc] = val;
                }
            }
        }
    }
}

// ---------------------------------------------------------------------------
// Split-K reduce: x[i] += part[i] + part[i+NN] + bias[i % ldc]
// ---------------------------------------------------------------------------
__global__ void reduce_splitk(const float* __restrict__ part,
                              const float* __restrict__ bias,
                              float* __restrict__ x, int NN, int ldc) {
    int idx = (blockIdx.x * 256 + threadIdx.x) * 4;
    float4 p0 = *(const float4*)(part + idx);
    float4 p1 = *(const float4*)(part + idx + NN);
    float4 xv = *(const float4*)(x + idx);
    float4 bv = *(const float4*)(bias + (idx % ldc));
    float4 o;
    o.x = xv.x + p0.x + p1.x + bv.x;
    o.y = xv.y + p0.y + p1.y + bv.y;
    o.z = xv.z + p0.z + p1.z + bv.z;
    o.w = xv.w + p0.w + p1.w + bv.w;
    *(float4*)(x + idx) = o;
}

// ---------------------------------------------------------------------------
// Row softmax over 1024 cols. grid (S, B*H), block 256.
// ---------------------------------------------------------------------------
__global__ void softmax_kernel(float* __restrict__ p) {
    float* pr = p + ((size_t)blockIdx.y * S_ + blockIdx.x) * S_;
    const int tid = threadIdx.x;
    __shared__ float red[256];

    float4 v = *(const float4*)(pr + tid * 4);
    float m = fmaxf(fmaxf(v.x, v.y), fmaxf(v.z, v.w));
    red[tid] = m;
    __syncthreads();
    for (int off = 128; off > 0; off >>= 1) {
        if (tid < off) red[tid] = fmaxf(red[tid], red[tid + off]);
        __syncthreads();
    }
    float mx = red[0];
    __syncthreads();

    float e0 = expf(v.x - mx), e1 = expf(v.y - mx);
    float e2 = expf(v.z - mx), e3 = expf(v.w - mx);
    red[tid] = e0 + e1 + e2 + e3;
    __syncthreads();
    for (int off = 128; off > 0; off >>= 1) {
        if (tid < off) red[tid] += red[tid + off];
        __syncthreads();
    }
    float inv = 1.0f / red[0];
    *(float4*)(pr + tid * 4) = make_float4(e0 * inv, e1 * inv, e2 * inv, e3 * inv);
}

// ---------------------------------------------------------------------------
// LayerNorm
// ---------------------------------------------------------------------------
__global__ void layernorm_kernel(const float* __restrict__ x,
                                 const float* __restrict__ g,
                                 const float* __restrict__ bb,
                                 float* __restrict__ out) {
    const int row = blockIdx.x;
    const int tid = threadIdx.x;
    const float* xr = x + (size_t)row * D_;
    __shared__ float rs[256];
    __shared__ float rq[256];

    float4 v = *(const float4*)(xr + tid * 4);
    float s  = v.x + v.y + v.z + v.w;
    float sq = v.x * v.x + v.y * v.y + v.z * v.z + v.w * v.w;
    rs[tid] = s; rq[tid] = sq;
    __syncthreads();
    for (int off = 128; off > 0; off >>= 1) {
        if (tid < off) { rs[tid] += rs[tid + off]; rq[tid] += rq[tid + off]; }
        __syncthreads();
    }
    float mu  = rs[0] * (1.0f / D_);
    float var = rq[0] * (1.0f / D_) - mu * mu;
    float rstd = rsqrtf(var + 1e-5f);

    int c = tid * 4;
    float4 gv = *(const float4*)(g + c);
    float4 bv = *(const float4*)(bb + c);
    float4 o;
    o.x = (v.x - mu) * rstd * gv.x + bv.x;
    o.y = (v.y - mu) * rstd * gv.y + bv.y;
    o.z = (v.z - mu) * rstd * gv.z + bv.z;
    o.w = (v.w - mu) * rstd * gv.w + bv.w;
    *(float4*)(out + (size_t)row * D_ + c) = o;
}

// ---------------------------------------------------------------------------
// Host launcher
// ---------------------------------------------------------------------------
extern "C" void kernel_launch(void* const* d_in, const int* in_sizes, int n_in,
                              void* d_out, int out_size) {
    const int*   idx   = (const int*)  d_in[0];
    const float* te    = (const float*)d_in[1];
    const float* pe    = (const float*)d_in[2];
    const float* wq    = (const float*)d_in[3];
    const float* bq    = (const float*)d_in[4];
    const float* wk    = (const float*)d_in[5];
    const float* bk    = (const float*)d_in[6];
    const float* wv    = (const float*)d_in[7];
    const float* bv    = (const float*)d_in[8];
    const float* wo    = (const float*)d_in[9];
    const float* bo    = (const float*)d_in[10];
    const float* ln2g  = (const float*)d_in[11];
    const float* ln2b  = (const float*)d_in[12];
    const float* w1    = (const float*)d_in[13];
    const float* b1    = (const float*)d_in[14];
    const float* w2    = (const float*)d_in[15];
    const float* b2    = (const float*)d_in[16];
    const float* lnfg  = (const float*)d_in[17];
    const float* lnfb  = (const float*)d_in[18];
    float* out = (float*)d_out;

    float *x, *q, *k, *v, *y, *ln, *h1, *p;
    cudaGetSymbolAddress((void**)&x,  g_x);
    cudaGetSymbolAddress((void**)&q,  g_q);
    cudaGetSymbolAddress((void**)&k,  g_k);
    cudaGetSymbolAddress((void**)&v,  g_v);
    cudaGetSymbolAddress((void**)&y,  g_y);
    cudaGetSymbolAddress((void**)&ln, g_ln);
    cudaGetSymbolAddress((void**)&h1, g_h1);
    cudaGetSymbolAddress((void**)&p,  g_p);

    embed_kernel<<<NTOK, 256>>>(idx, te, pe, x);

    const dim3 gQKV(D_ / 128, NTOK / 128, 3);       // (8,16,3) = 384
    const dim3 gSK (D_ / 128, NTOK / 128, 2);       // (8,16,2) = 256
    const dim3 gF  (DFF_ / 128, NTOK / 128);        // (32,16)  = 512
    const dim3 gSc (S_ / 128, S_ / 128, B_ * H_);   // (8,8,32) = 2048
    const dim3 gAv (1, S_ / 128, B_ * H_);          // (1,8,32) = 256
    const dim3 gSm (S_, B_ * H_);
    const dim3 gLg ((V_ + 127) / 128, NTOK / 128);  // (393,16) = 6288

    const long long SD = (long long)S_ * D_;
    const long long SS = (long long)S_ * S_;
    const int NN = NTOK * D_;                        // split-K slab elements

    for (int l = 0; l < L_; l++) {
        const float* wq_l = wq + (size_t)l * D_ * D_;
        const float* wk_l = wk + (size_t)l * D_ * D_;
        const float* wv_l = wv + (size_t)l * D_ * D_;
        const float* wo_l = wo + (size_t)l * D_ * D_;
        const float* w1_l = w1 + (size_t)l * D_ * DFF_;
        const float* w2_l = w2 + (size_t)l * DFF_ * D_;

        // q/k/v = x @ W + b (fused, z selects)
        mma_gemm<128,false,false,false,false,false,false,true,1><<<gQKV, 256>>>(
            x, wq_l, bq + l * D_, nullptr, q, NTOK, D_, D_, D_, D_, D_,
            1, 0,0, 0,0, 0,0,
            wk_l, bk + l * D_, k, wv_l, bv + l * D_, v);

        // P = mask(scale(q @ k^T)) per (b,h)
        mma_gemm<128,true,false,false,true,false,false,false,1><<<gSc, 256>>>(
            q, k, nullptr, nullptr, p, S_, S_, DK_, D_, D_, S_,
            H_, SD, 64, SD, 64, 16 * SS, SS,
            nullptr, nullptr, nullptr, nullptr, nullptr, nullptr);

        softmax_kernel<<<gSm, 256>>>(p);

        // y = P @ v per (b,h)
        mma_gemm<64,false,false,false,false,false,true,false,1><<<gAv, 256>>>(
            p, v, nullptr, nullptr, y, S_, DK_, S_, S_, D_, D_,
            H_, 16 * SS, SS, SD, 64, SD, 64,
            nullptr, nullptr, nullptr, nullptr, nullptr, nullptr);

        // x += y @ wo + bo  (split-K2 into p, then reduce)
        mma_gemm<128,false,false,false,false,false,false,false,2><<<gSK, 256>>>(
            y, wo_l, nullptr, nullptr, p, NTOK, D_, D_, D_, D_, D_,
            1, 0,0, 0,0, 0,0,
            nullptr, nullptr, nullptr, nullptr, nullptr, nullptr);
        reduce_splitk<<<NN / 1024, 256>>>(p, bo + l * D_, x, NN, D_);

        layernorm_kernel<<<NTOK, 256>>>(x, ln2g + l * D_, ln2b + l * D_, ln);

        // h1 = gelu(ln @ w1 + b1)
        mma_gemm<128,false,true,false,false,false,false,false,1><<<gF, 256>>>(
            ln, w1_l, b1 + l * DFF_, nullptr, h1, NTOK, DFF_, D_, D_, DFF_, DFF_,
            1, 0,0, 0,0, 0,0,
            nullptr, nullptr, nullptr, nullptr, nullptr, nullptr);

        // x += h1 @ w2 + b2  (split-K2 into p, then reduce)
        mma_gemm<128,false,false,false,false,false,false,false,2><<<gSK, 256>>>(
            h1, w2_l, nullptr, nullptr, p, NTOK, D_, DFF_, DFF_, D_, D_,
            1, 0,0, 0,0, 0,0,
            nullptr, nullptr, nullptr, nullptr, nullptr, nullptr);
        reduce_splitk<<<NN / 1024, 256>>>(p, b2 + l * D_, x, NN, D_);
    }

    layernorm_kernel<<<NTOK, 256>>>(x, lnfg, lnfb, ln);

    // logits = ln @ te^T
    mma_gemm<128,true,false,false,false,true,false,false,1><<<gLg, 256>>>(
        ln, te, nullptr, nullptr, out, NTOK, V_, D_, D_, D_, V_,
        1, 0,0, 0,0, 0,0,
        nullptr, nullptr, nullptr, nullptr, nullptr, nullptr);
}

// round 4
// speedup vs baseline: 3.0270x; 1.0805x over previous
#include <cuda_runtime.h>
#include <cuda_bf16.h>
#include <math.h>

#define D_   1024
#define H_   16
#define V_   50257
#define L_   4
#define B_   2
#define S_   1024
#define DK_  64
#define DFF_ 4096
#define NTOK (B_ * S_)
#define NEGF (-3.402823466e38f)

// ---------------------------------------------------------------------------
// Device scratch
// ---------------------------------------------------------------------------
__device__ float g_x [NTOK * D_];
__device__ float g_q [NTOK * D_];
__device__ float g_k [NTOK * D_];
__device__ float g_v [NTOK * D_];
__device__ float g_y [NTOK * D_];
__device__ float g_ln[NTOK * D_];
__device__ float g_h1[NTOK * DFF_];
__device__ float g_p [2 * NTOK * D_];   // split-K partials

__device__ __forceinline__ float gelu_exact(float v) {
    return 0.5f * v * (1.0f + erff(v * 0.70710678118654752440f));
}

__device__ __forceinline__ unsigned f2tf32(float x) {
    unsigned u;
    asm("cvt.rna.tf32.f32 %0, %1;" : "=r"(u) : "f"(x));
    return u;
}
__device__ __forceinline__ float f2tf32f(float x) { return __uint_as_float(f2tf32(x)); }

__device__ __forceinline__ void mma_tf32(float* c, const unsigned* a, const unsigned* b) {
    asm volatile(
        "mma.sync.aligned.m16n8k8.row.col.f32.tf32.tf32.f32 "
        "{%0,%1,%2,%3},{%4,%5,%6,%7},{%8,%9},{%0,%1,%2,%3};"
        : "+f"(c[0]), "+f"(c[1]), "+f"(c[2]), "+f"(c[3])
        : "r"(a[0]), "r"(a[1]), "r"(a[2]), "r"(a[3]), "r"(b[0]), "r"(b[1]));
}

// ---------------------------------------------------------------------------
// Embedding
// ---------------------------------------------------------------------------
__global__ void embed_kernel(const int* __restrict__ idx,
                             const float* __restrict__ te,
                             const float* __restrict__ pe,
                             float* __restrict__ x) {
    int row = blockIdx.x;
    int s   = row % S_;
    int tok = idx[row];
    int c   = threadIdx.x * 4;
    float4 t = *(const float4*)(te + (size_t)tok * D_ + c);
    float4 p = *(const float4*)(pe + (size_t)s   * D_ + c);
    *(float4*)(x + (size_t)row * D_ + c) =
        make_float4(t.x + p.x, t.y + p.y, t.z + p.z, t.w + p.w);
}

// ---------------------------------------------------------------------------
// Fused flash attention (causal), tf32 MMA, online softmax.
// grid (8, B*H), block 256 (8 warps x 16 rows). Q rows 128/CTA, K-tiles of 64.
// q,k,v,y layout: [b, s, h, d], row stride H*DK = 1024.
// ---------------------------------------------------------------------------
__global__ void __launch_bounds__(256, 2)
flash_attn(const float* __restrict__ q, const float* __restrict__ k,
           const float* __restrict__ v, float* __restrict__ y)
{
    constexpr int KSTR = 76, VSTR = 76;
    __shared__ float Ks[64 * KSTR];
    __shared__ float Vs[64 * VSTR];

    const int xmap[8] = {0, 7, 1, 6, 2, 5, 3, 4};   // pair heavy+light tiles
    const int m0  = xmap[blockIdx.x] * 128;
    const int bh  = blockIdx.y;
    const int b   = bh >> 4, h = bh & 15;
    const int tid = threadIdx.x;
    const int wid = tid >> 5, lane = tid & 31;
    const int g   = lane >> 2, tq = lane & 3;
    const int rowbase = wid * 16;
    const int r0 = m0 + rowbase + g;
    const int r8 = r0 + 8;
    const int RS = H_ * DK_;     // 1024

    // ---- Q fragments, pre-scaled by 1/8 (exact), tf32 ----
    unsigned qf[8][4];
    {
        const float* q0 = q + (size_t)(b * S_ + r0) * RS + h * DK_;
        const float* q8 = q0 + 8 * RS;
        #pragma unroll
        for (int ks = 0; ks < 8; ks++) {
            qf[ks][0] = f2tf32(0.125f * q0[8 * ks + tq]);
            qf[ks][1] = f2tf32(0.125f * q8[8 * ks + tq]);
            qf[ks][2] = f2tf32(0.125f * q0[8 * ks + tq + 4]);
            qf[ks][3] = f2tf32(0.125f * q8[8 * ks + tq + 4]);
        }
    }

    float o[8][4];
    #pragma unroll
    for (int j = 0; j < 8; j++)
        #pragma unroll
        for (int c = 0; c < 4; c++) o[j][c] = 0.0f;
    float mg = NEGF, m8 = NEGF, lg = 0.0f, l8 = 0.0f;

    const int srcA = (lane & ~3) | (tq >> 1);
    const int srcB = srcA + 2;
    const bool odd = (tq & 1);

    const int krr = tid >> 2;            // 0..63
    const int kcc = (tid & 3) * 16;      // 0,16,32,48
    const int ntiles = m0 / 64 + 2;

    for (int jt = 0; jt < ntiles; jt++) {
        const int t0 = jt * 64;

        // ---- load K,V tile (64x64 each) as tf32 ----
        {
            const float* ksrc = k + (size_t)(b * S_ + t0 + krr) * RS + h * DK_ + kcc;
            const float* vsrc = v + (size_t)(b * S_ + t0 + krr) * RS + h * DK_ + kcc;
            #pragma unroll
            for (int u = 0; u < 4; u++) {
                float4 a = *(const float4*)(ksrc + u * 4);
                float4 c = *(const float4*)(vsrc + u * 4);
                float4 at, ct;
                at.x = f2tf32f(a.x); at.y = f2tf32f(a.y); at.z = f2tf32f(a.z); at.w = f2tf32f(a.w);
                ct.x = f2tf32f(c.x); ct.y = f2tf32f(c.y); ct.z = f2tf32f(c.z); ct.w = f2tf32f(c.w);
                *(float4*)&Ks[krr * KSTR + kcc + u * 4] = at;
                *(float4*)&Vs[krr * VSTR + kcc + u * 4] = ct;
            }
        }
        __syncthreads();

        // ---- S = (Q/8) @ K^T ----
        float s[8][4];
        #pragma unroll
        for (int j = 0; j < 8; j++)
            #pragma unroll
            for (int c = 0; c < 4; c++) s[j][c] = 0.0f;

        #pragma unroll
        for (int ks = 0; ks < 8; ks++) {
            #pragma unroll
            for (int jn = 0; jn < 8; jn++) {
                unsigned bf[2];
                bf[0] = __float_as_uint(Ks[(8 * jn + g) * KSTR + 8 * ks + tq]);
                bf[1] = __float_as_uint(Ks[(8 * jn + g) * KSTR + 8 * ks + tq + 4]);
                mma_tf32(s[jn], qf[ks], bf);
            }
        }

        // ---- causal mask (only near-diagonal tiles) ----
        if (t0 + 63 > m0) {
            #pragma unroll
            for (int jn = 0; jn < 8; jn++) {
                int c0 = t0 + 8 * jn + 2 * tq;
                if (c0     > r0) s[jn][0] = NEGF;
                if (c0 + 1 > r0) s[jn][1] = NEGF;
                if (c0     > r8) s[jn][2] = NEGF;
                if (c0 + 1 > r8) s[jn][3] = NEGF;
            }
        }

        // ---- online softmax ----
        float tmg = NEGF, tm8 = NEGF;
        #pragma unroll
        for (int jn = 0; jn < 8; jn++) {
            tmg = fmaxf(tmg, fmaxf(s[jn][0], s[jn][1]));
            tm8 = fmaxf(tm8, fmaxf(s[jn][2], s[jn][3]));
        }
        tmg = fmaxf(tmg, __shfl_xor_sync(0xffffffffu, tmg, 1));
        tmg = fmaxf(tmg, __shfl_xor_sync(0xffffffffu, tmg, 2));
        tm8 = fmaxf(tm8, __shfl_xor_sync(0xffffffffu, tm8, 1));
        tm8 = fmaxf(tm8, __shfl_xor_sync(0xffffffffu, tm8, 2));

        float mgn = fmaxf(mg, tmg), m8n = fmaxf(m8, tm8);
        float ag = expf(mg - mgn), a8 = expf(m8 - m8n);

        float rsg = 0.0f, rs8 = 0.0f;
        #pragma unroll
        for (int jn = 0; jn < 8; jn++) {
            s[jn][0] = expf(s[jn][0] - mgn);
            s[jn][1] = expf(s[jn][1] - mgn);
            s[jn][2] = expf(s[jn][2] - m8n);
            s[jn][3] = expf(s[jn][3] - m8n);
            rsg += s[jn][0] + s[jn][1];
            rs8 += s[jn][2] + s[jn][3];
        }
        rsg += __shfl_xor_sync(0xffffffffu, rsg, 1);
        rsg += __shfl_xor_sync(0xffffffffu, rsg, 2);
        rs8 += __shfl_xor_sync(0xffffffffu, rs8, 1);
        rs8 += __shfl_xor_sync(0xffffffffu, rs8, 2);

        lg = lg * ag + rsg;
        l8 = l8 * a8 + rs8;
        mg = mgn; m8 = m8n;

        #pragma unroll
        for (int jd = 0; jd < 8; jd++) {
            o[jd][0] *= ag; o[jd][1] *= ag;
            o[jd][2] *= a8; o[jd][3] *= a8;
        }

        // ---- O += P @ V (A fragments via intra-quad shuffles) ----
        #pragma unroll
        for (int kt = 0; kt < 8; kt++) {
            unsigned af[4];
            {
                float x0 = __shfl_sync(0xffffffffu, s[kt][0], srcA);
                float x1 = __shfl_sync(0xffffffffu, s[kt][1], srcA);
                float y0 = __shfl_sync(0xffffffffu, s[kt][2], srcA);
                float y1 = __shfl_sync(0xffffffffu, s[kt][3], srcA);
                float z0 = __shfl_sync(0xffffffffu, s[kt][0], srcB);
                float z1 = __shfl_sync(0xffffffffu, s[kt][1], srcB);
                float w0 = __shfl_sync(0xffffffffu, s[kt][2], srcB);
                float w1 = __shfl_sync(0xffffffffu, s[kt][3], srcB);
                af[0] = f2tf32(odd ? x1 : x0);
                af[1] = f2tf32(odd ? y1 : y0);
                af[2] = f2tf32(odd ? z1 : z0);
                af[3] = f2tf32(odd ? w1 : w0);
            }
            #pragma unroll
            for (int jd = 0; jd < 8; jd++) {
                unsigned bf[2];
                bf[0] = __float_as_uint(Vs[(8 * kt + tq) * VSTR + 8 * jd + g]);
                bf[1] = __float_as_uint(Vs[(8 * kt + tq + 4) * VSTR + 8 * jd + g]);
                mma_tf32(o[jd], af, bf);
            }
        }
        __syncthreads();
    }

    // ---- normalize + write ----
    float ig = 1.0f / lg, i8 = 1.0f / l8;
    float* y0 = y + (size_t)(b * S_ + r0) * RS + h * DK_;
    float* y8 = y0 + 8 * RS;
    #pragma unroll
    for (int jd = 0; jd < 8; jd++) {
        *(float2*)(y0 + 8 * jd + 2 * tq) = make_float2(o[jd][0] * ig, o[jd][1] * ig);
        *(float2*)(y8 + 8 * jd + 2 * tq) = make_float2(o[jd][2] * i8, o[jd][3] * i8);
    }
}

// ---------------------------------------------------------------------------
// TF32 MMA GEMM, double-buffered (dense GEMMs only now).
// ---------------------------------------------------------------------------
template <int BN, bool BTRANS, bool GELU_ACT, bool NGUARD, bool QKV, int SPLITK>
__global__ void __launch_bounds__(256, 2)
mma_gemm(const float* __restrict__ Ag, const float* __restrict__ Bg,
         const float* __restrict__ biasg, float* __restrict__ Cg,
         int M, int N, int K, int lda, int ldb, int ldc,
         const float* Bg2, const float* bias2, float* Cg2,
         const float* Bg3, const float* bias3, float* Cg3)
{
    constexpr int BM = 128, BK = 16;
    constexpr int ASTR = 20;
    constexpr int BSTR = BN + 8;
    constexpr int WN   = 2;
    constexpr int WMC  = 4;
    constexpr int WROWS = 32;
    constexpr int MT   = 2;
    constexpr int NT   = (BN / WN) / 8;

    __shared__ float As[2 * BM * ASTR];
    __shared__ float Bs[2 * BK * BSTR];

    const int tid  = threadIdx.x;
    const int wid  = tid >> 5;
    const int lane = tid & 31;
    const int g    = lane >> 2;
    const int tq   = lane & 3;
    const int m0   = blockIdx.y * BM;
    const int n0   = blockIdx.x * BN;
    const int z    = blockIdx.z;

    const float* A = Ag;
    const float* B = Bg;
    const float* bias = biasg;
    float* C = Cg;

    if (QKV) {
        if (z == 1) { B = Bg2; bias = bias2; C = Cg2; }
        else if (z == 2) { B = Bg3; bias = bias3; C = Cg3; }
    } else if (SPLITK > 1) {
        C = Cg + (long long)z * M * ldc;
    }

    const int rowbase = (wid % WMC) * WROWS;
    const int colbase = (wid / WMC) * (BN / WN);

    float acc[MT][NT][4];
    #pragma unroll
    for (int i = 0; i < MT; i++)
        #pragma unroll
        for (int j = 0; j < NT; j++)
            #pragma unroll
            for (int q = 0; q < 4; q++) acc[i][j][q] = 0.0f;

    int kbeg = 0, kend = K;
    if (SPLITK > 1) { kbeg = z * (K / SPLITK); kend = kbeg + K / SPLITK; }
    const int ntiles = (kend - kbeg) / BK;

    const int ar = tid >> 1, ac = (tid & 1) * 8;
    const int bk = tid >> 4;
    const int bc128 = (tid & 15) * 8;
    const int tn = tid >> 1, tk = (tid & 1) * 8;

    auto ldg_tile = [&](int k0, float4& a0, float4& a1, float4& b0, float4& b1) {
        const float* srcA = A + (long long)(m0 + ar) * lda + k0 + ac;
        a0 = *(const float4*)srcA;
        a1 = *(const float4*)(srcA + 4);
        if (!BTRANS) {
            const float* srcB = B + (long long)(k0 + bk) * ldb + n0 + bc128;
            b0 = *(const float4*)srcB;
            b1 = *(const float4*)(srcB + 4);
        } else {
            b0 = make_float4(0.f, 0.f, 0.f, 0.f);
            b1 = make_float4(0.f, 0.f, 0.f, 0.f);
            bool ok = !NGUARD || (n0 + tn) < N;
            if (ok) {
                const float* srcB = B + (long long)(n0 + tn) * ldb + k0 + tk;
                b0 = *(const float4*)srcB;
                b1 = *(const float4*)(srcB + 4);
            }
        }
    };

    auto sts_tile = [&](int buf, float4 a0, float4 a1, float4 b0, float4 b1) {
        float* as = As + buf * BM * ASTR;
        float* bs = Bs + buf * BK * BSTR;
        float4 w0, w1;
        w0.x = f2tf32f(a0.x); w0.y = f2tf32f(a0.y); w0.z = f2tf32f(a0.z); w0.w = f2tf32f(a0.w);
        w1.x = f2tf32f(a1.x); w1.y = f2tf32f(a1.y); w1.z = f2tf32f(a1.z); w1.w = f2tf32f(a1.w);
        *(float4*)&as[ar * ASTR + ac]     = w0;
        *(float4*)&as[ar * ASTR + ac + 4] = w1;
        if (!BTRANS) {
            float4 u0, u1;
            u0.x = f2tf32f(b0.x); u0.y = f2tf32f(b0.y); u0.z = f2tf32f(b0.z); u0.w = f2tf32f(b0.w);
            u1.x = f2tf32f(b1.x); u1.y = f2tf32f(b1.y); u1.z = f2tf32f(b1.z); u1.w = f2tf32f(b1.w);
            *(float4*)&bs[bk * BSTR + bc128]     = u0;
            *(float4*)&bs[bk * BSTR + bc128 + 4] = u1;
        } else {
            bs[(tk + 0) * BSTR + tn] = f2tf32f(b0.x);
            bs[(tk + 1) * BSTR + tn] = f2tf32f(b0.y);
            bs[(tk + 2) * BSTR + tn] = f2tf32f(b0.z);
            bs[(tk + 3) * BSTR + tn] = f2tf32f(b0.w);
            bs[(tk + 4) * BSTR + tn] = f2tf32f(b1.x);
            bs[(tk + 5) * BSTR + tn] = f2tf32f(b1.y);
            bs[(tk + 6) * BSTR + tn] = f2tf32f(b1.z);
            bs[(tk + 7) * BSTR + tn] = f2tf32f(b1.w);
        }
    };

    {
        float4 a0, a1, b0, b1;
        ldg_tile(kbeg, a0, a1, b0, b1);
        sts_tile(0, a0, a1, b0, b1);
    }
    __syncthreads();

    for (int t = 0; t < ntiles; t++) {
        const int cur = t & 1;
        const bool has_next = (t + 1) < ntiles;
        float4 a0, a1, b0, b1;
        if (has_next) ldg_tile(kbeg + (t + 1) * BK, a0, a1, b0, b1);

        const float* as = As + cur * BM * ASTR;
        const float* bs = Bs + cur * BK * BSTR;
        #pragma unroll
        for (int ks = 0; ks < BK; ks += 8) {
            unsigned af[MT][4];
            #pragma unroll
            for (int i = 0; i < MT; i++) {
                int r = rowbase + i * 16 + g;
                af[i][0] = __float_as_uint(as[r * ASTR + ks + tq]);
                af[i][1] = __float_as_uint(as[(r + 8) * ASTR + ks + tq]);
                af[i][2] = __float_as_uint(as[r * ASTR + ks + tq + 4]);
                af[i][3] = __float_as_uint(as[(r + 8) * ASTR + ks + tq + 4]);
            }
            unsigned bf[NT][2];
            #pragma unroll
            for (int j = 0; j < NT; j++) {
                int c = colbase + j * 8 + g;
                bf[j][0] = __float_as_uint(bs[(ks + tq) * BSTR + c]);
                bf[j][1] = __float_as_uint(bs[(ks + tq + 4) * BSTR + c]);
            }
            #pragma unroll
            for (int i = 0; i < MT; i++)
                #pragma unroll
                for (int j = 0; j < NT; j++)
                    mma_tf32(acc[i][j], af[i], bf[j]);
        }

        if (has_next) sts_tile(cur ^ 1, a0, a1, b0, b1);
        __syncthreads();
    }

    #pragma unroll
    for (int i = 0; i < MT; i++) {
        #pragma unroll
        for (int j = 0; j < NT; j++) {
            int r = m0 + rowbase + i * 16 + g;
            int c = n0 + colbase + j * 8 + tq * 2;
            #pragma unroll
            for (int q = 0; q < 4; q++) {
                int rr = r + (q >> 1) * 8;
                int cc = c + (q & 1);
                if (NGUARD && cc >= N) continue;
                float val = acc[i][j][q];
                if (SPLITK > 1) {
                    C[(long long)rr * ldc + cc] = val;
                } else {
                    if (bias) val += bias[cc];
                    if (GELU_ACT) val = gelu_exact(val);
                    C[(long long)rr * ldc + cc] = val;
                }
            }
        }
    }
}

// ---------------------------------------------------------------------------
// Split-K reduce: x[i] += part[i] + part[i+NN] + bias[i % ldc]
// ---------------------------------------------------------------------------
__global__ void reduce_splitk(const float* __restrict__ part,
                              const float* __restrict__ bias,
                              float* __restrict__ x, int NN, int ldc) {
    int idx = (blockIdx.x * 256 + threadIdx.x) * 4;
    float4 p0 = *(const float4*)(part + idx);
    float4 p1 = *(const float4*)(part + idx + NN);
    float4 xv = *(const float4*)(x + idx);
    float4 bv = *(const float4*)(bias + (idx % ldc));
    float4 o;
    o.x = xv.x + p0.x + p1.x + bv.x;
    o.y = xv.y + p0.y + p1.y + bv.y;
    o.z = xv.z + p0.z + p1.z + bv.z;
    o.w = xv.w + p0.w + p1.w + bv.w;
    *(float4*)(x + idx) = o;
}

// ---------------------------------------------------------------------------
// LayerNorm
// ---------------------------------------------------------------------------
__global__ void layernorm_kernel(const float* __restrict__ x,
                                 const float* __restrict__ g,
                                 const float* __restrict__ bb,
                                 float* __restrict__ out) {
    const int row = blockIdx.x;
    const int tid = threadIdx.x;
    const float* xr = x + (size_t)row * D_;
    __shared__ float rs[256];
    __shared__ float rq[256];

    float4 v = *(const float4*)(xr + tid * 4);
    float s  = v.x + v.y + v.z + v.w;
    float sq = v.x * v.x + v.y * v.y + v.z * v.z + v.w * v.w;
    rs[tid] = s; rq[tid] = sq;
    __syncthreads();
    for (int off = 128; off > 0; off >>= 1) {
        if (tid < off) { rs[tid] += rs[tid + off]; rq[tid] += rq[tid + off]; }
        __syncthreads();
    }
    float mu  = rs[0] * (1.0f / D_);
    float var = rq[0] * (1.0f / D_) - mu * mu;
    float rstd = rsqrtf(var + 1e-5f);

    int c = tid * 4;
    float4 gv = *(const float4*)(g + c);
    float4 bv = *(const float4*)(bb + c);
    float4 o;
    o.x = (v.x - mu) * rstd * gv.x + bv.x;
    o.y = (v.y - mu) * rstd * gv.y + bv.y;
    o.z = (v.z - mu) * rstd * gv.z + bv.z;
    o.w = (v.w - mu) * rstd * gv.w + bv.w;
    *(float4*)(out + (size_t)row * D_ + c) = o;
}

// ---------------------------------------------------------------------------
// Host launcher
// ---------------------------------------------------------------------------
extern "C" void kernel_launch(void* const* d_in, const int* in_sizes, int n_in,
                              void* d_out, int out_size) {
    const int*   idx   = (const int*)  d_in[0];
    const float* te    = (const float*)d_in[1];
    const float* pe    = (const float*)d_in[2];
    const float* wq    = (const float*)d_in[3];
    const float* bq    = (const float*)d_in[4];
    const float* wk    = (const float*)d_in[5];
    const float* bk    = (const float*)d_in[6];
    const float* wv    = (const float*)d_in[7];
    const float* bv    = (const float*)d_in[8];
    const float* wo    = (const float*)d_in[9];
    const float* bo    = (const float*)d_in[10];
    const float* ln2g  = (const float*)d_in[11];
    const float* ln2b  = (const float*)d_in[12];
    const float* w1    = (const float*)d_in[13];
    const float* b1    = (const float*)d_in[14];
    const float* w2    = (const float*)d_in[15];
    const float* b2    = (const float*)d_in[16];
    const float* lnfg  = (const float*)d_in[17];
    const float* lnfb  = (const float*)d_in[18];
    float* out = (float*)d_out;

    float *x, *q, *k, *v, *y, *ln, *h1, *p;
    cudaGetSymbolAddress((void**)&x,  g_x);
    cudaGetSymbolAddress((void**)&q,  g_q);
    cudaGetSymbolAddress((void**)&k,  g_k);
    cudaGetSymbolAddress((void**)&v,  g_v);
    cudaGetSymbolAddress((void**)&y,  g_y);
    cudaGetSymbolAddress((void**)&ln, g_ln);
    cudaGetSymbolAddress((void**)&h1, g_h1);
    cudaGetSymbolAddress((void**)&p,  g_p);

    embed_kernel<<<NTOK, 256>>>(idx, te, pe, x);

    const dim3 gQKV(D_ / 128, NTOK / 128, 3);
    const dim3 gSK (D_ / 128, NTOK / 128, 2);
    const dim3 gF  (DFF_ / 128, NTOK / 128);
    const dim3 gFA (S_ / 128, B_ * H_);
    const dim3 gLg ((V_ + 127) / 128, NTOK / 128);
    const int NN = NTOK * D_;

    for (int l = 0; l < L_; l++) {
        const float* wq_l = wq + (size_t)l * D_ * D_;
        const float* wk_l = wk + (size_t)l * D_ * D_;
        const float* wv_l = wv + (size_t)l * D_ * D_;
        const float* wo_l = wo + (size_t)l * D_ * D_;
        const float* w1_l = w1 + (size_t)l * D_ * DFF_;
        const float* w2_l = w2 + (size_t)l * DFF_ * D_;

        // q/k/v = x @ W + b (fused)
        mma_gemm<128,false,false,false,true,1><<<gQKV, 256>>>(
            x, wq_l, bq + l * D_, q, NTOK, D_, D_, D_, D_, D_,
            wk_l, bk + l * D_, k, wv_l, bv + l * D_, v);

        // fused causal attention -> y
        flash_attn<<<gFA, 256>>>(q, k, v, y);

        // x += y @ wo + bo (split-K2)
        mma_gemm<128,false,false,false,false,2><<<gSK, 256>>>(
            y, wo_l, nullptr, p, NTOK, D_, D_, D_, D_, D_,
            nullptr, nullptr, nullptr, nullptr, nullptr, nullptr);
        reduce_splitk<<<NN / 1024, 256>>>(p, bo + l * D_, x, NN, D_);

        layernorm_kernel<<<NTOK, 256>>>(x, ln2g + l * D_, ln2b + l * D_, ln);

        // h1 = gelu(ln @ w1 + b1)
        mma_gemm<128,false,true,false,false,1><<<gF, 256>>>(
            ln, w1_l, b1 + l * DFF_, h1, NTOK, DFF_, D_, D_, DFF_, DFF_,
            nullptr, nullptr, nullptr, nullptr, nullptr, nullptr);

        // x += h1 @ w2 + b2 (split-K2)
        mma_gemm<128,false,false,false,false,2><<<gSK, 256>>>(
            h1, w2_l, nullptr, p, NTOK, D_, DFF_, DFF_, D_, D_,
            nullptr, nullptr, nullptr, nullptr, nullptr, nullptr);
        reduce_splitk<<<NN / 1024, 256>>>(p, b2 + l * D_, x, NN, D_);
    }

    layernorm_kernel<<<NTOK, 256>>>(x, lnfg, lnfb, ln);

    // logits = ln @ te^T
    mma_gemm<128,true,false,true,false,1><<<gLg, 256>>>(
        ln, te, nullptr, out, NTOK, V_, D_, D_, D_, V_,
        nullptr, nullptr, nullptr, nullptr, nullptr, nullptr);
}

// round 5
// speedup vs baseline: 3.7828x; 1.2497x over previous
#include <cuda_runtime.h>
#include <cuda_bf16.h>
#include <math.h>

#define D_   1024
#define H_   16
#define V_   50257
#define L_   4
#define B_   2
#define S_   1024
#define DK_  64
#define DFF_ 4096
#define NTOK (B_ * S_)
#define NEGF (-3.402823466e38f)

// ---------------------------------------------------------------------------
// Device scratch
// ---------------------------------------------------------------------------
__device__ float g_x [NTOK * D_];
__device__ float g_xr[NTOK * D_];        // tf32-rounded shadow of x (QKV A operand)
__device__ float g_q [NTOK * D_];
__device__ float g_k [NTOK * D_];
__device__ float g_v [NTOK * D_];
__device__ float g_y [NTOK * D_];
__device__ float g_ln[NTOK * D_];
__device__ float g_h1[NTOK * DFF_];
__device__ float g_p [2 * NTOK * D_];    // split-K partials
// tf32-prerounded weights
__device__ float g_wq[L_ * D_ * D_];
__device__ float g_wk[L_ * D_ * D_];
__device__ float g_wv[L_ * D_ * D_];
__device__ float g_wo[L_ * D_ * D_];
__device__ float g_w1[L_ * D_ * DFF_];
__device__ float g_w2[L_ * DFF_ * D_];
__device__ float g_te[(size_t)V_ * D_];

__device__ __forceinline__ float gelu_exact(float v) {
    return 0.5f * v * (1.0f + erff(v * 0.70710678118654752440f));
}

__device__ __forceinline__ unsigned f2tf32(float x) {
    unsigned u;
    asm("cvt.rna.tf32.f32 %0, %1;" : "=r"(u) : "f"(x));
    return u;
}
__device__ __forceinline__ float f2tf32f(float x) { return __uint_as_float(f2tf32(x)); }

__device__ __forceinline__ void mma_tf32(float* c, const unsigned* a, const unsigned* b) {
    asm volatile(
        "mma.sync.aligned.m16n8k8.row.col.f32.tf32.tf32.f32 "
        "{%0,%1,%2,%3},{%4,%5,%6,%7},{%8,%9},{%0,%1,%2,%3};"
        : "+f"(c[0]), "+f"(c[1]), "+f"(c[2]), "+f"(c[3])
        : "r"(a[0]), "r"(a[1]), "r"(a[2]), "r"(a[3]), "r"(b[0]), "r"(b[1]));
}

__device__ __forceinline__ void cp16(float* s, const float* g, bool pred) {
    unsigned sa = (unsigned)__cvta_generic_to_shared(s);
    int sz = pred ? 16 : 0;
    asm volatile("cp.async.cg.shared.global [%0], [%1], 16, %2;\n"
                 :: "r"(sa), "l"(g), "r"(sz));
}
__device__ __forceinline__ void cp_commit() {
    asm volatile("cp.async.commit_group;\n" ::: "memory");
}

// ---------------------------------------------------------------------------
// Prepass: round fp32 -> tf32 bits (RNA), elementwise float4.
// ---------------------------------------------------------------------------
__global__ void cvt_tf32_kernel(const float* __restrict__ in, float* __restrict__ outp) {
    int i = blockIdx.x * 256 + threadIdx.x;
    float4 v = ((const float4*)in)[i];
    float4 w;
    w.x = f2tf32f(v.x); w.y = f2tf32f(v.y); w.z = f2tf32f(v.z); w.w = f2tf32f(v.w);
    ((float4*)outp)[i] = w;
}

// ---------------------------------------------------------------------------
// Embedding: x and rounded shadow xr
// ---------------------------------------------------------------------------
__global__ void embed_kernel(const int* __restrict__ idx,
                             const float* __restrict__ te,
                             const float* __restrict__ pe,
                             float* __restrict__ x, float* __restrict__ xr) {
    int row = blockIdx.x;
    int s   = row % S_;
    int tok = idx[row];
    int c   = threadIdx.x * 4;
    float4 t = *(const float4*)(te + (size_t)tok * D_ + c);
    float4 p = *(const float4*)(pe + (size_t)s   * D_ + c);
    float4 o = make_float4(t.x + p.x, t.y + p.y, t.z + p.z, t.w + p.w);
    *(float4*)(x + (size_t)row * D_ + c) = o;
    float4 r;
    r.x = f2tf32f(o.x); r.y = f2tf32f(o.y); r.z = f2tf32f(o.z); r.w = f2tf32f(o.w);
    *(float4*)(xr + (size_t)row * D_ + c) = r;
}

// ---------------------------------------------------------------------------
// Fused flash attention (unchanged math; epilogue rounds y to tf32)
// ---------------------------------------------------------------------------
__global__ void __launch_bounds__(256, 2)
flash_attn(const float* __restrict__ q, const float* __restrict__ k,
           const float* __restrict__ v, float* __restrict__ y)
{
    constexpr int KSTR = 76, VSTR = 76;
    __shared__ float Ks[64 * KSTR];
    __shared__ float Vs[64 * VSTR];

    const int xmap[8] = {0, 7, 1, 6, 2, 5, 3, 4};
    const int m0  = xmap[blockIdx.x] * 128;
    const int bh  = blockIdx.y;
    const int b   = bh >> 4, h = bh & 15;
    const int tid = threadIdx.x;
    const int wid = tid >> 5, lane = tid & 31;
    const int g   = lane >> 2, tq = lane & 3;
    const int rowbase = wid * 16;
    const int r0 = m0 + rowbase + g;
    const int r8 = r0 + 8;
    const int RS = H_ * DK_;

    unsigned qf[8][4];
    {
        const float* q0 = q + (size_t)(b * S_ + r0) * RS + h * DK_;
        const float* q8 = q0 + 8 * RS;
        #pragma unroll
        for (int ks = 0; ks < 8; ks++) {
            qf[ks][0] = f2tf32(0.125f * q0[8 * ks + tq]);
            qf[ks][1] = f2tf32(0.125f * q8[8 * ks + tq]);
            qf[ks][2] = f2tf32(0.125f * q0[8 * ks + tq + 4]);
            qf[ks][3] = f2tf32(0.125f * q8[8 * ks + tq + 4]);
        }
    }

    float o[8][4];
    #pragma unroll
    for (int j = 0; j < 8; j++)
        #pragma unroll
        for (int c = 0; c < 4; c++) o[j][c] = 0.0f;
    float mg = NEGF, m8 = NEGF, lg = 0.0f, l8 = 0.0f;

    const int srcA = (lane & ~3) | (tq >> 1);
    const int srcB = srcA + 2;
    const bool odd = (tq & 1);

    const int krr = tid >> 2;
    const int kcc = (tid & 3) * 16;
    const int ntiles = m0 / 64 + 2;

    for (int jt = 0; jt < ntiles; jt++) {
        const int t0 = jt * 64;
        {
            const float* ksrc = k + (size_t)(b * S_ + t0 + krr) * RS + h * DK_ + kcc;
            const float* vsrc = v + (size_t)(b * S_ + t0 + krr) * RS + h * DK_ + kcc;
            #pragma unroll
            for (int u = 0; u < 4; u++) {
                float4 a = *(const float4*)(ksrc + u * 4);
                float4 c = *(const float4*)(vsrc + u * 4);
                float4 at, ct;
                at.x = f2tf32f(a.x); at.y = f2tf32f(a.y); at.z = f2tf32f(a.z); at.w = f2tf32f(a.w);
                ct.x = f2tf32f(c.x); ct.y = f2tf32f(c.y); ct.z = f2tf32f(c.z); ct.w = f2tf32f(c.w);
                *(float4*)&Ks[krr * KSTR + kcc + u * 4] = at;
                *(float4*)&Vs[krr * VSTR + kcc + u * 4] = ct;
            }
        }
        __syncthreads();

        float s[8][4];
        #pragma unroll
        for (int j = 0; j < 8; j++)
            #pragma unroll
            for (int c = 0; c < 4; c++) s[j][c] = 0.0f;

        #pragma unroll
        for (int ks = 0; ks < 8; ks++) {
            #pragma unroll
            for (int jn = 0; jn < 8; jn++) {
                unsigned bf[2];
                bf[0] = __float_as_uint(Ks[(8 * jn + g) * KSTR + 8 * ks + tq]);
                bf[1] = __float_as_uint(Ks[(8 * jn + g) * KSTR + 8 * ks + tq + 4]);
                mma_tf32(s[jn], qf[ks], bf);
            }
        }

        if (t0 + 63 > m0) {
            #pragma unroll
            for (int jn = 0; jn < 8; jn++) {
                int c0 = t0 + 8 * jn + 2 * tq;
                if (c0     > r0) s[jn][0] = NEGF;
                if (c0 + 1 > r0) s[jn][1] = NEGF;
                if (c0     > r8) s[jn][2] = NEGF;
                if (c0 + 1 > r8) s[jn][3] = NEGF;
            }
        }

        float tmg = NEGF, tm8 = NEGF;
        #pragma unroll
        for (int jn = 0; jn < 8; jn++) {
            tmg = fmaxf(tmg, fmaxf(s[jn][0], s[jn][1]));
            tm8 = fmaxf(tm8, fmaxf(s[jn][2], s[jn][3]));
        }
        tmg = fmaxf(tmg, __shfl_xor_sync(0xffffffffu, tmg, 1));
        tmg = fmaxf(tmg, __shfl_xor_sync(0xffffffffu, tmg, 2));
        tm8 = fmaxf(tm8, __shfl_xor_sync(0xffffffffu, tm8, 1));
        tm8 = fmaxf(tm8, __shfl_xor_sync(0xffffffffu, tm8, 2));

        float mgn = fmaxf(mg, tmg), m8n = fmaxf(m8, tm8);
        float ag = expf(mg - mgn), a8 = expf(m8 - m8n);

        float rsg = 0.0f, rs8 = 0.0f;
        #pragma unroll
        for (int jn = 0; jn < 8; jn++) {
            s[jn][0] = expf(s[jn][0] - mgn);
            s[jn][1] = expf(s[jn][1] - mgn);
            s[jn][2] = expf(s[jn][2] - m8n);
            s[jn][3] = expf(s[jn][3] - m8n);
            rsg += s[jn][0] + s[jn][1];
            rs8 += s[jn][2] + s[jn][3];
        }
        rsg += __shfl_xor_sync(0xffffffffu, rsg, 1);
        rsg += __shfl_xor_sync(0xffffffffu, rsg, 2);
        rs8 += __shfl_xor_sync(0xffffffffu, rs8, 1);
        rs8 += __shfl_xor_sync(0xffffffffu, rs8, 2);

        lg = lg * ag + rsg;
        l8 = l8 * a8 + rs8;
        mg = mgn; m8 = m8n;

        #pragma unroll
        for (int jd = 0; jd < 8; jd++) {
            o[jd][0] *= ag; o[jd][1] *= ag;
            o[jd][2] *= a8; o[jd][3] *= a8;
        }

        #pragma unroll
        for (int kt = 0; kt < 8; kt++) {
            unsigned af[4];
            {
                float x0 = __shfl_sync(0xffffffffu, s[kt][0], srcA);
                float x1 = __shfl_sync(0xffffffffu, s[kt][1], srcA);
                float y0 = __shfl_sync(0xffffffffu, s[kt][2], srcA);
                float y1 = __shfl_sync(0xffffffffu, s[kt][3], srcA);
                float z0 = __shfl_sync(0xffffffffu, s[kt][0], srcB);
                float z1 = __shfl_sync(0xffffffffu, s[kt][1], srcB);
                float w0 = __shfl_sync(0xffffffffu, s[kt][2], srcB);
                float w1 = __shfl_sync(0xffffffffu, s[kt][3], srcB);
                af[0] = f2tf32(odd ? x1 : x0);
                af[1] = f2tf32(odd ? y1 : y0);
                af[2] = f2tf32(odd ? z1 : z0);
                af[3] = f2tf32(odd ? w1 : w0);
            }
            #pragma unroll
            for (int jd = 0; jd < 8; jd++) {
                unsigned bf[2];
                bf[0] = __float_as_uint(Vs[(8 * kt + tq) * VSTR + 8 * jd + g]);
                bf[1] = __float_as_uint(Vs[(8 * kt + tq + 4) * VSTR + 8 * jd + g]);
                mma_tf32(o[jd], af, bf);
            }
        }
        __syncthreads();
    }

    float ig = 1.0f / lg, i8 = 1.0f / l8;
    float* y0 = y + (size_t)(b * S_ + r0) * RS + h * DK_;
    float* y8 = y0 + 8 * RS;
    #pragma unroll
    for (int jd = 0; jd < 8; jd++) {
        *(float2*)(y0 + 8 * jd + 2 * tq) =
            make_float2(f2tf32f(o[jd][0] * ig), f2tf32f(o[jd][1] * ig));
        *(float2*)(y8 + 8 * jd + 2 * tq) =
            make_float2(f2tf32f(o[jd][2] * i8), f2tf32f(o[jd][3] * i8));
    }
}

// ---------------------------------------------------------------------------
// TF32 MMA GEMM: cp.async 3-stage pipeline, operands pre-rounded (zero cvt).
//   BTRANS : B stored [N,K] row-major (logits); smem n-major
//   NGUARD : logits; also swaps grid mapping (m on blockIdx.x for te L2 reuse)
//   QKV    : z selects (B,bias,C) triple
//   SPLITK : z partitions K; raw partial store to C + z*M*ldc
// BM=BN=128, BK=16, 256 threads, 8 warps (warp tile 32x64).
// ---------------------------------------------------------------------------
template <bool BTRANS, bool GELU_ACT, bool NGUARD, bool QKV, int SPLITK>
__global__ void __launch_bounds__(256, 2)
mma_gemm(const float* __restrict__ Ag, const float* __restrict__ Bg,
         const float* __restrict__ biasg, float* __restrict__ Cg,
         int M, int N, int K, int lda, int ldb, int ldc,
         const float* Bg2, const float* bias2, float* Cg2,
         const float* Bg3, const float* bias3, float* Cg3)
{
    constexpr int BM = 128, BN = 128, BK = 16, STAGES = 3;
    constexpr int ASTR = 20;
    constexpr int BSTR = BTRANS ? 20 : (BN + 8);
    constexpr int ASZ  = BM * ASTR;
    constexpr int BSZ  = BTRANS ? (BN * BSTR) : (BK * BSTR);

    extern __shared__ float smem[];
    float* AsB = smem;
    float* BsB = smem + STAGES * ASZ;

    const int tid  = threadIdx.x;
    const int wid  = tid >> 5;
    const int lane = tid & 31;
    const int g    = lane >> 2;
    const int tq   = lane & 3;
    const int m0   = NGUARD ? blockIdx.x * BM : blockIdx.y * BM;
    const int n0   = NGUARD ? blockIdx.y * BN : blockIdx.x * BN;
    const int z    = blockIdx.z;

    const float* A = Ag;
    const float* B = Bg;
    const float* bias = biasg;
    float* C = Cg;

    if (QKV) {
        if (z == 1) { B = Bg2; bias = bias2; C = Cg2; }
        else if (z == 2) { B = Bg3; bias = bias3; C = Cg3; }
    } else if (SPLITK > 1) {
        C = Cg + (long long)z * M * ldc;
    }

    const int rowbase = (wid & 3) * 32;
    const int colbase = (wid >> 2) * 64;

    float acc[2][8][4];
    #pragma unroll
    for (int i = 0; i < 2; i++)
        #pragma unroll
        for (int j = 0; j < 8; j++)
            #pragma unroll
            for (int q = 0; q < 4; q++) acc[i][j][q] = 0.0f;

    int kbeg = 0, kend = K;
    if (SPLITK > 1) { kbeg = z * (K / SPLITK); kend = kbeg + K / SPLITK; }
    const int ntiles = (kend - kbeg) / BK;

    auto issue_stage = [&](int stage, int k0) {
        float* as = AsB + stage * ASZ;
        float* bs = BsB + stage * BSZ;
        #pragma unroll
        for (int i = 0; i < 2; i++) {
            int c = tid + i * 256;
            int row = c >> 2, col = (c & 3) * 4;
            cp16(&as[row * ASTR + col],
                 A + (long long)(m0 + row) * lda + k0 + col, true);
        }
        if (!BTRANS) {
            #pragma unroll
            for (int i = 0; i < 2; i++) {
                int c = tid + i * 256;
                int kr = c >> 5, nc = (c & 31) * 4;
                cp16(&bs[kr * BSTR + nc],
                     B + (long long)(k0 + kr) * ldb + n0 + nc, true);
            }
        } else {
            #pragma unroll
            for (int i = 0; i < 2; i++) {
                int c = tid + i * 256;
                int nr = c >> 2, kc = (c & 3) * 4;
                bool ok = !NGUARD || (n0 + nr) < N;
                cp16(&bs[nr * BSTR + kc],
                     B + (long long)(n0 + nr) * ldb + k0 + kc, ok);
            }
        }
        cp_commit();
    };

    issue_stage(0, kbeg);
    if (ntiles > 1) issue_stage(1, kbeg + BK);

    for (int t = 0; t < ntiles; t++) {
        if (t == ntiles - 1)
            asm volatile("cp.async.wait_group 0;\n" ::: "memory");
        else
            asm volatile("cp.async.wait_group 1;\n" ::: "memory");
        __syncthreads();

        if (t + 2 < ntiles) issue_stage((t + 2) % STAGES, kbeg + (t + 2) * BK);

        const float* as = AsB + (t % STAGES) * ASZ;
        const float* bs = BsB + (t % STAGES) * BSZ;

        #pragma unroll
        for (int ks = 0; ks < BK; ks += 8) {
            unsigned af[2][4];
            #pragma unroll
            for (int i = 0; i < 2; i++) {
                int r = rowbase + i * 16 + g;
                af[i][0] = __float_as_uint(as[r * ASTR + ks + tq]);
                af[i][1] = __float_as_uint(as[(r + 8) * ASTR + ks + tq]);
                af[i][2] = __float_as_uint(as[r * ASTR + ks + tq + 4]);
                af[i][3] = __float_as_uint(as[(r + 8) * ASTR + ks + tq + 4]);
            }
            unsigned bf[8][2];
            #pragma unroll
            for (int j = 0; j < 8; j++) {
                int c = colbase + j * 8 + g;
                if (!BTRANS) {
                    bf[j][0] = __float_as_uint(bs[(ks + tq) * BSTR + c]);
                    bf[j][1] = __float_as_uint(bs[(ks + tq + 4) * BSTR + c]);
                } else {
                    bf[j][0] = __float_as_uint(bs[c * BSTR + ks + tq]);
                    bf[j][1] = __float_as_uint(bs[c * BSTR + ks + tq + 4]);
                }
            }
            #pragma unroll
            for (int i = 0; i < 2; i++)
                #pragma unroll
                for (int j = 0; j < 8; j++)
                    mma_tf32(acc[i][j], af[i], bf[j]);
        }
    }

    // epilogue
    #pragma unroll
    for (int i = 0; i < 2; i++) {
        #pragma unroll
        for (int j = 0; j < 8; j++) {
            int r = m0 + rowbase + i * 16 + g;
            int c = n0 + colbase + j * 8 + tq * 2;
            #pragma unroll
            for (int q = 0; q < 4; q++) {
                int rr = r + (q >> 1) * 8;
                int cc = c + (q & 1);
                if (NGUARD && cc >= N) continue;
                float val = acc[i][j][q];
                if (SPLITK > 1) {
                    C[(long long)rr * ldc + cc] = val;
                } else {
                    if (bias) val += bias[cc];
                    if (GELU_ACT) val = f2tf32f(gelu_exact(val));
                    C[(long long)rr * ldc + cc] = val;
                }
            }
        }
    }
}

// ---------------------------------------------------------------------------
// Split-K reduce: x += partials + bias; also writes tf32 shadow xr
// ---------------------------------------------------------------------------
__global__ void reduce_splitk(const float* __restrict__ part,
                              const float* __restrict__ bias,
                              float* __restrict__ x, float* __restrict__ xr,
                              int NN, int ldc) {
    int idx = (blockIdx.x * 256 + threadIdx.x) * 4;
    float4 p0 = *(const float4*)(part + idx);
    float4 p1 = *(const float4*)(part + idx + NN);
    float4 xv = *(const float4*)(x + idx);
    float4 bv = *(const float4*)(bias + (idx % ldc));
    float4 o;
    o.x = xv.x + p0.x + p1.x + bv.x;
    o.y = xv.y + p0.y + p1.y + bv.y;
    o.z = xv.z + p0.z + p1.z + bv.z;
    o.w = xv.w + p0.w + p1.w + bv.w;
    *(float4*)(x + idx) = o;
    float4 r;
    r.x = f2tf32f(o.x); r.y = f2tf32f(o.y); r.z = f2tf32f(o.z); r.w = f2tf32f(o.w);
    *(float4*)(xr + idx) = r;
}

// ---------------------------------------------------------------------------
// LayerNorm: output tf32-rounded (consumed only by GEMMs)
// ---------------------------------------------------------------------------
__global__ void layernorm_kernel(const float* __restrict__ x,
                                 const float* __restrict__ g,
                                 const float* __restrict__ bb,
                                 float* __restrict__ out) {
    const int row = blockIdx.x;
    const int tid = threadIdx.x;
    const float* xr = x + (size_t)row * D_;
    __shared__ float rs[256];
    __shared__ float rq[256];

    float4 v = *(const float4*)(xr + tid * 4);
    float s  = v.x + v.y + v.z + v.w;
    float sq = v.x * v.x + v.y * v.y + v.z * v.z + v.w * v.w;
    rs[tid] = s; rq[tid] = sq;
    __syncthreads();
    for (int off = 128; off > 0; off >>= 1) {
        if (tid < off) { rs[tid] += rs[tid + off]; rq[tid] += rq[tid + off]; }
        __syncthreads();
    }
    float mu  = rs[0] * (1.0f / D_);
    float var = rq[0] * (1.0f / D_) - mu * mu;
    float rstd = rsqrtf(var + 1e-5f);

    int c = tid * 4;
    float4 gv = *(const float4*)(g + c);
    float4 bv = *(const float4*)(bb + c);
    float4 o;
    o.x = f2tf32f((v.x - mu) * rstd * gv.x + bv.x);
    o.y = f2tf32f((v.y - mu) * rstd * gv.y + bv.y);
    o.z = f2tf32f((v.z - mu) * rstd * gv.z + bv.z);
    o.w = f2tf32f((v.w - mu) * rstd * gv.w + bv.w);
    *(float4*)(out + (size_t)row * D_ + c) = o;
}

// ---------------------------------------------------------------------------
// Host launcher
// ---------------------------------------------------------------------------
extern "C" void kernel_launch(void* const* d_in, const int* in_sizes, int n_in,
                              void* d_out, int out_size) {
    const int*   idx   = (const int*)  d_in[0];
    const float* te    = (const float*)d_in[1];
    const float* pe    = (const float*)d_in[2];
    const float* wq    = (const float*)d_in[3];
    const float* bq    = (const float*)d_in[4];
    const float* wk    = (const float*)d_in[5];
    const float* bk    = (const float*)d_in[6];
    const float* wv    = (const float*)d_in[7];
    const float* bv    = (const float*)d_in[8];
    const float* wo    = (const float*)d_in[9];
    const float* bo    = (const float*)d_in[10];
    const float* ln2g  = (const float*)d_in[11];
    const float* ln2b  = (const float*)d_in[12];
    const float* w1    = (const float*)d_in[13];
    const float* b1    = (const float*)d_in[14];
    const float* w2    = (const float*)d_in[15];
    const float* b2    = (const float*)d_in[16];
    const float* lnfg  = (const float*)d_in[17];
    const float* lnfb  = (const float*)d_in[18];
    float* out = (float*)d_out;

    float *x, *xr, *q, *k, *v, *y, *ln, *h1, *p;
    float *cwq, *cwk, *cwv, *cwo, *cw1, *cw2, *cte;
    cudaGetSymbolAddress((void**)&x,  g_x);
    cudaGetSymbolAddress((void**)&xr, g_xr);
    cudaGetSymbolAddress((void**)&q,  g_q);
    cudaGetSymbolAddress((void**)&k,  g_k);
    cudaGetSymbolAddress((void**)&v,  g_v);
    cudaGetSymbolAddress((void**)&y,  g_y);
    cudaGetSymbolAddress((void**)&ln, g_ln);
    cudaGetSymbolAddress((void**)&h1, g_h1);
    cudaGetSymbolAddress((void**)&p,  g_p);
    cudaGetSymbolAddress((void**)&cwq, g_wq);
    cudaGetSymbolAddress((void**)&cwk, g_wk);
    cudaGetSymbolAddress((void**)&cwv, g_wv);
    cudaGetSymbolAddress((void**)&cwo, g_wo);
    cudaGetSymbolAddress((void**)&cw1, g_w1);
    cudaGetSymbolAddress((void**)&cw2, g_w2);
    cudaGetSymbolAddress((void**)&cte, g_te);

    // smem sizes for pipelined GEMM
    const int ASZ = 128 * 20, BSZ_NT = 16 * 136, BSZ_T = 128 * 20;
    const size_t smem_nt = 3 * (ASZ + BSZ_NT) * sizeof(float);   // 56832
    const size_t smem_t  = 3 * (ASZ + BSZ_T) * sizeof(float);    // 61440

    auto kq  = mma_gemm<false, false, false, true,  1>;
    auto ksk = mma_gemm<false, false, false, false, 2>;
    auto kw1 = mma_gemm<false, true,  false, false, 1>;
    auto klg = mma_gemm<true,  false, true,  false, 1>;
    cudaFuncSetAttribute(kq,  cudaFuncAttributeMaxDynamicSharedMemorySize, (int)smem_nt);
    cudaFuncSetAttribute(ksk, cudaFuncAttributeMaxDynamicSharedMemorySize, (int)smem_nt);
    cudaFuncSetAttribute(kw1, cudaFuncAttributeMaxDynamicSharedMemorySize, (int)smem_nt);
    cudaFuncSetAttribute(klg, cudaFuncAttributeMaxDynamicSharedMemorySize, (int)smem_t);

    // ---- weight prepass (fp32 -> tf32 bits) ----
    const int NW = L_ * D_ * D_ / 4;        // 1,048,576 float4s
    const int NF = L_ * D_ * DFF_ / 4;      // 4,194,304
    const int NT4 = V_ * D_ / 4;            // 12,865,792
    cvt_tf32_kernel<<<NW / 256, 256>>>(wq, cwq);
    cvt_tf32_kernel<<<NW / 256, 256>>>(wk, cwk);
    cvt_tf32_kernel<<<NW / 256, 256>>>(wv, cwv);
    cvt_tf32_kernel<<<NW / 256, 256>>>(wo, cwo);
    cvt_tf32_kernel<<<NF / 256, 256>>>(w1, cw1);
    cvt_tf32_kernel<<<NF / 256, 256>>>(w2, cw2);
    cvt_tf32_kernel<<<NT4 / 256, 256>>>(te, cte);

    embed_kernel<<<NTOK, 256>>>(idx, te, pe, x, xr);

    const dim3 gQKV(D_ / 128, NTOK / 128, 3);
    const dim3 gSK (D_ / 128, NTOK / 128, 2);
    const dim3 gF  (DFF_ / 128, NTOK / 128);
    const dim3 gFA (S_ / 128, B_ * H_);
    const dim3 gLg (NTOK / 128, (V_ + 127) / 128);   // m fastest for te L2 reuse
    const int NN = NTOK * D_;

    for (int l = 0; l < L_; l++) {
        const float* wq_l = cwq + (size_t)l * D_ * D_;
        const float* wk_l = cwk + (size_t)l * D_ * D_;
        const float* wv_l = cwv + (size_t)l * D_ * D_;
        const float* wo_l = cwo + (size_t)l * D_ * D_;
        const float* w1_l = cw1 + (size_t)l * D_ * DFF_;
        const float* w2_l = cw2 + (size_t)l * DFF_ * D_;

        kq<<<gQKV, 256, smem_nt>>>(
            xr, wq_l, bq + l * D_, q, NTOK, D_, D_, D_, D_, D_,
            wk_l, bk + l * D_, k, wv_l, bv + l * D_, v);

        flash_attn<<<gFA, 256>>>(q, k, v, y);

        ksk<<<gSK, 256, smem_nt>>>(
            y, wo_l, nullptr, p, NTOK, D_, D_, D_, D_, D_,
            nullptr, nullptr, nullptr, nullptr, nullptr, nullptr);
        reduce_splitk<<<NN / 1024, 256>>>(p, bo + l * D_, x, xr, NN, D_);

        layernorm_kernel<<<NTOK, 256>>>(x, ln2g + l * D_, ln2b + l * D_, ln);

        kw1<<<gF, 256, smem_nt>>>(
            ln, w1_l, b1 + l * DFF_, h1, NTOK, DFF_, D_, D_, DFF_, DFF_,
            nullptr, nullptr, nullptr, nullptr, nullptr, nullptr);

        ksk<<<gSK, 256, smem_nt>>>(
            h1, w2_l, nullptr, p, NTOK, D_, DFF_, DFF_, D_, D_,
            nullptr, nullptr, nullptr, nullptr, nullptr, nullptr);
        reduce_splitk<<<NN / 1024, 256>>>(p, b2 + l * D_, x, xr, NN, D_);
    }

    layernorm_kernel<<<NTOK, 256>>>(x, lnfg, lnfb, ln);

    klg<<<gLg, 256, smem_t>>>(
        ln, cte, nullptr, out, NTOK, V_, D_, D_, D_, V_,
        nullptr, nullptr, nullptr, nullptr, nullptr, nullptr);
}